// round 2
// baseline (speedup 1.0000x reference)
#include <cuda_runtime.h>
#include <math.h>

#define N_NODES 10000
#define N_EDGES 160000
#define FDIM    256
#define HCW     768   // hcat width: [h(256) | temb(256) | emb_pcs(256)]
#define ABW     512   // [A(256) | B(256)] per node

// -------- device scratch (static allocation only; no cudaMalloc allowed) ----
__device__ __align__(16) float g_hcat[N_NODES * HCW];   // 30.7 MB
__device__ __align__(16) float g_AB  [N_NODES * ABW];   // 20.5 MB
__device__ __align__(16) float g_seg [N_NODES * FDIM];  // 10.2 MB (also reused as N x 3)
__device__ __align__(16) float g_Wc  [HCW * ABW];       // 1.5 MB combined first-layer weight

// -------- float atomic max via int max / uint min trick ---------------------
__device__ __forceinline__ void atomicMaxF(float* addr, float v) {
    if (v >= 0.0f) atomicMax((int*)addr, __float_as_int(v));
    else           atomicMin((unsigned int*)addr, __float_as_uint(v));
}

// -------- packed f32x2 helpers ---------------------------------------------
__device__ __forceinline__ unsigned long long dup_f32(float a) {
    unsigned long long r;
    asm("mov.b64 %0, {%1, %1};" : "=l"(r) : "f"(a));
    return r;
}
__device__ __forceinline__ float2 unpack_f32x2(unsigned long long v) {
    float2 r;
    asm("mov.b64 {%0, %1}, %2;" : "=f"(r.x), "=f"(r.y) : "l"(v));
    return r;
}
__device__ __forceinline__ void fma_f32x2(unsigned long long& acc,
                                          unsigned long long a,
                                          unsigned long long b) {
    asm("fma.rn.f32x2 %0, %1, %2, %0;" : "+l"(acc) : "l"(a), "l"(b));
}

// ============================================================================
// temb: v = [sin(2pi*t*fw), cos(2pi*t*fw)] (256) ; temb = silu(v @ teW + teb)
// 8 nodes per block for teW reuse. Writes hcat[:, 256:512].
// ============================================================================
__global__ void temb_kernel(const float* __restrict__ t,
                            const float* __restrict__ fw,
                            const float* __restrict__ teW,
                            const float* __restrict__ teb) {
    __shared__ float v[8][256];
    int j = threadIdx.x;
    int i0 = blockIdx.x * 8;
    if (j < 128) {
        float f = fw[j] * 6.283185307179586f;
#pragma unroll
        for (int r = 0; r < 8; r++) {
            float p = t[i0 + r] * f;
            v[r][j]       = sinf(p);
            v[r][j + 128] = cosf(p);
        }
    }
    __syncthreads();
    float acc[8];
    float bb = teb[j];
#pragma unroll
    for (int r = 0; r < 8; r++) acc[r] = bb;
    for (int k = 0; k < 256; k++) {
        float w = teW[k * 256 + j];
#pragma unroll
        for (int r = 0; r < 8; r++) acc[r] = fmaf(v[r][k], w, acc[r]);
    }
#pragma unroll
    for (int r = 0; r < 8; r++) {
        float a = acc[r];
        a = a / (1.0f + expf(-a));                 // silu
        g_hcat[(size_t)(i0 + r) * HCW + 256 + j] = a;
    }
}

// ============================================================================
// encoder: h = x @ enc_W + enc_b (D=3); also copy emb_pcs into hcat[:,512:768]
// ============================================================================
__global__ void enc_kernel(const float* __restrict__ x,
                           const float* __restrict__ encW,
                           const float* __restrict__ encb,
                           const float* __restrict__ emb) {
    int i = blockIdx.x, j = threadIdx.x;
    float h = encb[j];
    h = fmaf(x[i * 3 + 0], encW[0 * 256 + j], h);
    h = fmaf(x[i * 3 + 1], encW[1 * 256 + j], h);
    h = fmaf(x[i * 3 + 2], encW[2 * 256 + j], h);
    g_hcat[(size_t)i * HCW + j]       = h;
    g_hcat[(size_t)i * HCW + 512 + j] = emb[(size_t)i * 256 + j];
}

// ============================================================================
// Wc prep: cols [0,256) = W1_top - W1_bot ; cols [256,512) = W1_bot
// W1 is [1536 x 256] row-major.
// ============================================================================
__global__ void prep_kernel(const float* __restrict__ W1) {
    int idx = blockIdx.x * 256 + threadIdx.x;   // 768*512 total
    int k = idx >> 9, j = idx & 511;
    float v;
    if (j < 256) v = W1[k * 256 + j] - W1[(768 + k) * 256 + j];
    else         v = W1[(768 + k) * 256 + (j - 256)];
    g_Wc[idx] = v;
}

// ============================================================================
// seg init to -inf
// ============================================================================
__global__ void init_kernel(int n) {
    int idx = blockIdx.x * 256 + threadIdx.x;
    if (idx < n) g_seg[idx] = __int_as_float(0xff800000);  // -inf
}

// ============================================================================
// 128x128x8 tiled GEMM, 8x8 register tiles, packed f32x2 FMA.
// GATHER=false: C[M=10000,512] = g_hcat[10000,768] @ g_Wc[768,512] -> g_AB
// GATHER=true : A-rows built on the fly z_e = relu(A[dst]+B[src]+b1),
//               C = Z[E,256] @ W2[256,256], epilogue atomicMax into g_seg[dst]
// ============================================================================
template <bool GATHER>
__global__ __launch_bounds__(256, 2)
void gemm_kernel(const float* __restrict__ Bparam, int ldb,
                 int M, int K,
                 const int* __restrict__ eidx,
                 const float* __restrict__ b1,
                 const float* __restrict__ b2) {
    __shared__ float As[8][128];
    __shared__ float Bs[8][128];
    __shared__ int   sSrc[128];
    __shared__ int   sDst[128];
    __shared__ float sB1[256];

    const float* A = GATHER ? g_AB : g_hcat;
    const float* B = GATHER ? Bparam : g_Wc;
    const int lda  = GATHER ? ABW : HCW;

    int tid = threadIdx.x;
    int m0 = blockIdx.x * 128;
    int n0 = blockIdx.y * 128;
    int tm = (tid >> 4) * 8;
    int tn = (tid & 15) * 8;

    if (GATHER) {
        if (tid < 128) {
            int e = m0 + tid;
            sSrc[tid] = eidx[e];
            sDst[tid] = eidx[N_EDGES + e];
        }
        sB1[tid] = b1[tid];   // K == 256 == blockDim
    }
    __syncthreads();

    unsigned long long acc[8][4];
#pragma unroll
    for (int i = 0; i < 8; i++)
#pragma unroll
        for (int j = 0; j < 4; j++) acc[i][j] = 0ull;

    int arow = tid >> 1;
    int akq  = (tid & 1) * 4;
    int bk   = tid >> 5;
    int bn   = (tid & 31) * 4;

    for (int k0 = 0; k0 < K; k0 += 8) {
        float4 av;
        if (GATHER) {
            int d = sDst[arow], s = sSrc[arow];
            float4 x1 = *(const float4*)&A[(size_t)d * ABW + k0 + akq];
            float4 x2 = *(const float4*)&A[(size_t)s * ABW + 256 + k0 + akq];
            float4 bb = *(const float4*)&sB1[k0 + akq];
            av.x = fmaxf(x1.x + x2.x + bb.x, 0.0f);
            av.y = fmaxf(x1.y + x2.y + bb.y, 0.0f);
            av.z = fmaxf(x1.z + x2.z + bb.z, 0.0f);
            av.w = fmaxf(x1.w + x2.w + bb.w, 0.0f);
        } else {
            int r = m0 + arow;
            if (r < M) av = *(const float4*)&A[(size_t)r * lda + k0 + akq];
            else       av = make_float4(0.f, 0.f, 0.f, 0.f);
        }
        float4 bv = *(const float4*)&B[(size_t)(k0 + bk) * ldb + n0 + bn];

        __syncthreads();   // previous iteration's compute must be done
        As[akq + 0][arow] = av.x;
        As[akq + 1][arow] = av.y;
        As[akq + 2][arow] = av.z;
        As[akq + 3][arow] = av.w;
        *(float4*)&Bs[bk][bn] = bv;
        __syncthreads();

#pragma unroll
        for (int k = 0; k < 8; k++) {
            float4 a0 = *(const float4*)&As[k][tm];
            float4 a1 = *(const float4*)&As[k][tm + 4];
            float ar[8] = {a0.x, a0.y, a0.z, a0.w, a1.x, a1.y, a1.z, a1.w};
            unsigned long long br[4];
#pragma unroll
            for (int j = 0; j < 4; j++)
                br[j] = *(const unsigned long long*)&Bs[k][tn + 2 * j];
#pragma unroll
            for (int i = 0; i < 8; i++) {
                unsigned long long ad = dup_f32(ar[i]);
#pragma unroll
                for (int j = 0; j < 4; j++) fma_f32x2(acc[i][j], ad, br[j]);
            }
        }
    }

    if (!GATHER) {
#pragma unroll
        for (int i = 0; i < 8; i++) {
            int r = m0 + tm + i;
            if (r < M) {
                float* Cr = &g_AB[(size_t)r * ABW + n0 + tn];
#pragma unroll
                for (int j = 0; j < 4; j++) {
                    float2 v = unpack_f32x2(acc[i][j]);
                    Cr[2 * j]     = v.x;
                    Cr[2 * j + 1] = v.y;
                }
            }
        }
    } else {
        float bb[8];
#pragma unroll
        for (int j = 0; j < 8; j++) bb[j] = b2[n0 + tn + j];
#pragma unroll
        for (int i = 0; i < 8; i++) {
            int d = sDst[tm + i];
            float* Sr = &g_seg[(size_t)d * FDIM + n0 + tn];
#pragma unroll
            for (int j = 0; j < 4; j++) {
                float2 v = unpack_f32x2(acc[i][j]);
                atomicMaxF(&Sr[2 * j],     v.x + bb[2 * j]);
                atomicMaxF(&Sr[2 * j + 1], v.y + bb[2 * j + 1]);
            }
        }
    }
}

// ============================================================================
// layer-3 edge kernel: W2 is [256 x 3]; one warp per edge, atomicMax into
// g_seg (as N x 3)
// ============================================================================
__global__ void edge3_kernel(const int* __restrict__ eidx,
                             const float* __restrict__ b1,
                             const float* __restrict__ W3,
                             const float* __restrict__ b2) {
    __shared__ float sW[768];
    __shared__ float sB1[256];
    int tid = threadIdx.x;
    for (int i = tid; i < 768; i += 256) sW[i] = W3[i];
    sB1[tid] = b1[tid];
    __syncthreads();
    int warp = tid >> 5, lane = tid & 31;
    int e = blockIdx.x * 8 + warp;
    int s = eidx[e], d = eidx[N_EDGES + e];
    const float* Ad = &g_AB[(size_t)d * ABW];
    const float* Bs = &g_AB[(size_t)s * ABW + 256];
    float s0 = 0.f, s1 = 0.f, s2 = 0.f;
#pragma unroll
    for (int k = lane; k < 256; k += 32) {
        float z = fmaxf(Ad[k] + Bs[k] + sB1[k], 0.0f);
        s0 = fmaf(z, sW[k * 3 + 0], s0);
        s1 = fmaf(z, sW[k * 3 + 1], s1);
        s2 = fmaf(z, sW[k * 3 + 2], s2);
    }
#pragma unroll
    for (int o = 16; o > 0; o >>= 1) {
        s0 += __shfl_down_sync(0xffffffff, s0, o);
        s1 += __shfl_down_sync(0xffffffff, s1, o);
        s2 += __shfl_down_sync(0xffffffff, s2, o);
    }
    if (lane == 0) {
        atomicMaxF(&g_seg[(size_t)d * 3 + 0], s0 + b2[0]);
        atomicMaxF(&g_seg[(size_t)d * 3 + 1], s1 + b2[1]);
        atomicMaxF(&g_seg[(size_t)d * 3 + 2], s2 + b2[2]);
    }
}

// ============================================================================
// finalize layers 1,2: hcat[:, :256] = relu(where(isfinite(seg), seg, 0))
//                     == (seg > 0) ? seg : 0
// ============================================================================
__global__ void fin12_kernel() {
    int i = blockIdx.x, j = threadIdx.x;
    float v = g_seg[(size_t)i * FDIM + j];
    g_hcat[(size_t)i * HCW + j] = (v > 0.0f) ? v : 0.0f;
}

// ============================================================================
// finalize layer 3: out = where(isfinite(seg), seg, 0) / (std + 1e-7)
// std = sqrt((SIGMA^(2t) - 1) / (2 ln SIGMA)), SIGMA = 25
// ============================================================================
__global__ void fin3_kernel(const float* __restrict__ t, float* __restrict__ out) {
    int idx = blockIdx.x * 256 + threadIdx.x;
    if (idx >= N_NODES * 3) return;
    int i = idx / 3;
    const float ln_sigma = 3.2188758248682006f;   // ln 25
    float tt = t[i];
    float sd = sqrtf((expf(2.0f * tt * ln_sigma) - 1.0f) / (2.0f * ln_sigma));
    float v = g_seg[idx];
    if (!isfinite(v)) v = 0.0f;
    out[idx] = v / (sd + 1e-7f);
}

// ============================================================================
extern "C" void kernel_launch(void* const* d_in, const int* in_sizes, int n_in,
                              void* d_out, int out_size) {
    const float* x    = (const float*)d_in[0];
    const int*   eidx = (const int*)d_in[1];    // int32! (JAX x64 disabled)
    const float* t    = (const float*)d_in[2];
    const float* emb  = (const float*)d_in[3];
    const float* encW = (const float*)d_in[4];
    const float* encb = (const float*)d_in[5];
    const float* fw   = (const float*)d_in[6];
    const float* teW  = (const float*)d_in[7];
    const float* teb  = (const float*)d_in[8];
    const float* W1[3] = {(const float*)d_in[9],  (const float*)d_in[13], (const float*)d_in[17]};
    const float* b1[3] = {(const float*)d_in[10], (const float*)d_in[14], (const float*)d_in[18]};
    const float* W2[3] = {(const float*)d_in[11], (const float*)d_in[15], (const float*)d_in[19]};
    const float* b2[3] = {(const float*)d_in[12], (const float*)d_in[16], (const float*)d_in[20]};
    float* out = (float*)d_out;

    (void)in_sizes; (void)n_in; (void)out_size;

    // temb + encoder build hcat = [h | temb | emb_pcs]
    temb_kernel<<<N_NODES / 8, 256>>>(t, fw, teW, teb);
    enc_kernel<<<N_NODES, 256>>>(x, encW, encb, emb);

    dim3 gNode((N_NODES + 127) / 128, ABW / 128);     // 79 x 4
    dim3 gEdge(N_EDGES / 128, FDIM / 128);            // 1250 x 2

    for (int l = 0; l < 3; l++) {
        // combined node GEMM: [A|B] = hcat @ Wc
        prep_kernel<<<(HCW * ABW) / 256, 256>>>(W1[l]);
        gemm_kernel<false><<<gNode, 256>>>(nullptr, ABW, N_NODES, HCW,
                                           nullptr, nullptr, nullptr);
        if (l < 2) {
            init_kernel<<<(N_NODES * FDIM) / 256, 256>>>(N_NODES * FDIM);
            gemm_kernel<true><<<gEdge, 256>>>(W2[l], FDIM, N_EDGES, FDIM,
                                              eidx, b1[l], b2[l]);
            fin12_kernel<<<N_NODES, 256>>>();
        } else {
            init_kernel<<<(N_NODES * 3 + 255) / 256, 256>>>(N_NODES * 3);
            edge3_kernel<<<N_EDGES / 8, 256>>>(eidx, b1[l], W2[l], b2[l]);
            fin3_kernel<<<(N_NODES * 3 + 255) / 256, 256>>>(t, out);
        }
    }
}

// round 5
// speedup vs baseline: 1.9353x; 1.9353x over previous
#include <cuda_runtime.h>
#include <cuda_bf16.h>
#include <math.h>
#include <stdint.h>

#define N_NODES 10000
#define N_EDGES 160000
#define FDIM    256
#define HCW     768   // hcat: [h(256) | temb(256) | emb_pcs(256)]
#define ABW     512   // [A(256) | B(256)] per node

// tiling: block 64(M) x 256(N), K-chunk 64, 8 warps (2m x 4n), warp 32x64
#define BM   64
#define BN   256
#define KC   64
#define A_TILE (BM * KC * 2)          // 8192 B per bf16 A tile
#define B_TILE (BN * KC * 2)          // 32768 B per bf16 B tile
#define DSMEM  (2 * A_TILE + 2 * B_TILE + 128)

// -------- device scratch ----------------------------------------------------
__device__ __align__(16) float g_hcat[N_NODES * HCW];
__device__ __align__(16) float g_AB  [N_NODES * ABW];
__device__ __align__(16) float g_seg [N_NODES * FDIM];
__device__ __align__(16) __nv_bfloat16 g_Bhi[512 * 768];   // W^T hi  [n][k]
__device__ __align__(16) __nv_bfloat16 g_Blo[512 * 768];   // W^T lo  [n][k]

// -------- helpers -----------------------------------------------------------
__device__ __forceinline__ void atomicMaxF(float* addr, float v) {
    if (v >= 0.0f) atomicMax((int*)addr, __float_as_int(v));
    else           atomicMin((unsigned int*)addr, __float_as_uint(v));
}
__device__ __forceinline__ uint32_t smem_u32(const void* p) {
    uint32_t a;
    asm("{ .reg .u64 t; cvta.to.shared.u64 t, %1; cvt.u32.u64 %0, t; }" : "=r"(a) : "l"(p));
    return a;
}
__device__ __forceinline__ void ldsm4(uint32_t* r, uint32_t addr) {
    asm volatile("ldmatrix.sync.aligned.m8n8.x4.shared.b16 {%0,%1,%2,%3}, [%4];"
                 : "=r"(r[0]), "=r"(r[1]), "=r"(r[2]), "=r"(r[3]) : "r"(addr));
}
__device__ __forceinline__ void mma16816(float* c, const uint32_t* a,
                                         uint32_t b0, uint32_t b1) {
    asm volatile("mma.sync.aligned.m16n8k16.row.col.f32.bf16.bf16.f32 "
                 "{%0,%1,%2,%3}, {%4,%5,%6,%7}, {%8,%9}, {%0,%1,%2,%3};"
                 : "+f"(c[0]), "+f"(c[1]), "+f"(c[2]), "+f"(c[3])
                 : "r"(a[0]), "r"(a[1]), "r"(a[2]), "r"(a[3]), "r"(b0), "r"(b1));
}
// bf16 hi/lo split of 2 floats -> packed uint32 hi, lo
__device__ __forceinline__ void split2(float z0, float z1, uint32_t& hi, uint32_t& lo) {
    __nv_bfloat16 h0 = __float2bfloat16(z0), h1 = __float2bfloat16(z1);
    __nv_bfloat16 l0 = __float2bfloat16(z0 - __bfloat162float(h0));
    __nv_bfloat16 l1 = __float2bfloat16(z1 - __bfloat162float(h1));
    hi = (uint32_t)__bfloat16_as_ushort(h0) | ((uint32_t)__bfloat16_as_ushort(h1) << 16);
    lo = (uint32_t)__bfloat16_as_ushort(l0) | ((uint32_t)__bfloat16_as_ushort(l1) << 16);
}

// ============================================================================
// small kernels (unchanged from passing R2 structure)
// ============================================================================
__global__ void temb_kernel(const float* __restrict__ t, const float* __restrict__ fw,
                            const float* __restrict__ teW, const float* __restrict__ teb) {
    __shared__ float v[8][256];
    int j = threadIdx.x, i0 = blockIdx.x * 8;
    if (j < 128) {
        float f = fw[j] * 6.283185307179586f;
#pragma unroll
        for (int r = 0; r < 8; r++) {
            float p = t[i0 + r] * f;
            v[r][j] = sinf(p); v[r][j + 128] = cosf(p);
        }
    }
    __syncthreads();
    float acc[8]; float bb = teb[j];
#pragma unroll
    for (int r = 0; r < 8; r++) acc[r] = bb;
    for (int k = 0; k < 256; k++) {
        float w = teW[k * 256 + j];
#pragma unroll
        for (int r = 0; r < 8; r++) acc[r] = fmaf(v[r][k], w, acc[r]);
    }
#pragma unroll
    for (int r = 0; r < 8; r++) {
        float a = acc[r];
        a = a / (1.0f + expf(-a));
        g_hcat[(size_t)(i0 + r) * HCW + 256 + j] = a;
    }
}

__global__ void enc_kernel(const float* __restrict__ x, const float* __restrict__ encW,
                           const float* __restrict__ encb, const float* __restrict__ emb) {
    int i = blockIdx.x, j = threadIdx.x;
    float h = encb[j];
    h = fmaf(x[i * 3 + 0], encW[0 * 256 + j], h);
    h = fmaf(x[i * 3 + 1], encW[1 * 256 + j], h);
    h = fmaf(x[i * 3 + 2], encW[2 * 256 + j], h);
    g_hcat[(size_t)i * HCW + j]       = h;
    g_hcat[(size_t)i * HCW + 512 + j] = emb[(size_t)i * 256 + j];
}

// Wc^T hi/lo [512 n][768 k]: n<256 -> W1top-W1bot col n ; else W1bot col n-256
__global__ void prepWc_kernel(const float* __restrict__ W1) {
    int idx = blockIdx.x * 256 + threadIdx.x;     // 512*768
    int n = idx / 768, k = idx % 768;
    float v = (n < 256) ? (W1[k * 256 + n] - W1[(768 + k) * 256 + n])
                        : W1[(768 + k) * 256 + (n - 256)];
    __nv_bfloat16 h = __float2bfloat16(v);
    g_Bhi[idx] = h;
    g_Blo[idx] = __float2bfloat16(v - __bfloat162float(h));
}

// W2^T hi/lo [256 n][256 k]
__global__ void prepW2_kernel(const float* __restrict__ W2) {
    int idx = blockIdx.x * 256 + threadIdx.x;     // 256*256
    int n = idx / 256, k = idx % 256;
    float v = W2[k * 256 + n];
    __nv_bfloat16 h = __float2bfloat16(v);
    g_Bhi[idx] = h;
    g_Blo[idx] = __float2bfloat16(v - __bfloat162float(h));
}

__global__ void init_kernel(int n) {
    int idx = blockIdx.x * 256 + threadIdx.x;
    if (idx < n) g_seg[idx] = __int_as_float(0xff800000);
}

// ============================================================================
// mma.sync bf16x3 GEMM (base-arch PTX: ldmatrix + mma.m16n8k16)
//   GATHER=false: g_AB[M,512] = hcat[M,768] @ Wc^T       (Kfull=768, 2 n-blocks)
//   GATHER=true : Z = relu(A[dst]+B[src]+b1) [64,256];  seg max= Z @ W2^T
// smem swizzle: 16B chunk kb (0..7) stored at kb ^ (row & 7)
// ============================================================================
template <bool GATHER>
__global__ __launch_bounds__(256, 2)
void mma_gemm(int M, int Kfull,
              const int* __restrict__ eidx,
              const float* __restrict__ b1,
              const float* __restrict__ b2) {
    extern __shared__ __align__(128) char dsm[];
    char* sbase = (char*)(((uintptr_t)dsm + 127) & ~(uintptr_t)127);
    char* sAhi = sbase;
    char* sAlo = sbase + A_TILE;
    char* sBhi = sbase + 2 * A_TILE;
    char* sBlo = sbase + 2 * A_TILE + B_TILE;
    const uint32_t uAhi = smem_u32(sAhi), uAlo = smem_u32(sAlo);
    const uint32_t uBhi = smem_u32(sBhi), uBlo = smem_u32(sBlo);

    __shared__ int   sSrc[BM];
    __shared__ int   sDst[BM];
    __shared__ __align__(16) float sB1[256];
    __shared__ float sB2[256];

    const int tid  = threadIdx.x;
    const int wid  = tid >> 5, lane = tid & 31;
    const int wm   = wid & 1;            // 0..1 (m group of 32)
    const int wn   = wid >> 1;           // 0..3 (n group of 64)
    const int m0   = blockIdx.x * BM;
    const int n0   = blockIdx.y * BN;
    const int nChunks = Kfull / KC;

    if (GATHER) {
        if (tid < BM) {
            int e = m0 + tid;
            sSrc[tid] = eidx[e];
            sDst[tid] = eidx[N_EDGES + e];
        }
        sB1[tid] = b1[tid];
        sB2[tid] = b2[tid];
    }

    float c[2][8][4];
#pragma unroll
    for (int i = 0; i < 2; i++)
#pragma unroll
        for (int j = 0; j < 8; j++)
#pragma unroll
            for (int q = 0; q < 4; q++) c[i][j][q] = 0.0f;

    // ldmatrix lane-address components (constant over chunks)
    const int lsub = lane >> 3, lrr = lane & 7;

    for (int cix = 0; cix < nChunks; cix++) {
        const int k0 = cix * KC;
        __syncthreads();   // smem reusable (prev mma done)

        // ---- build A tile: 4 threads per row, 16 floats each ----
        {
            int r  = tid >> 2;            // 0..63
            int tq = tid & 3;             // k quarter (16 floats)
            float z[16];
            if (GATHER) {
                int d = sDst[r], s = sSrc[r];
                const float4* pA = (const float4*)(g_AB + (size_t)d * ABW + k0 + tq * 16);
                const float4* pB = (const float4*)(g_AB + (size_t)s * ABW + 256 + k0 + tq * 16);
                const float4* pb = (const float4*)(sB1 + k0 + tq * 16);
#pragma unroll
                for (int q = 0; q < 4; q++) {
                    float4 a = pA[q], b = pB[q], bi = pb[q];
                    z[4 * q + 0] = fmaxf(a.x + b.x + bi.x, 0.0f);
                    z[4 * q + 1] = fmaxf(a.y + b.y + bi.y, 0.0f);
                    z[4 * q + 2] = fmaxf(a.z + b.z + bi.z, 0.0f);
                    z[4 * q + 3] = fmaxf(a.w + b.w + bi.w, 0.0f);
                }
            } else {
                int row = m0 + r;
                if (row < M) {
                    const float4* p = (const float4*)(g_hcat + (size_t)row * HCW + k0 + tq * 16);
#pragma unroll
                    for (int q = 0; q < 4; q++) {
                        float4 a = p[q];
                        z[4 * q + 0] = a.x; z[4 * q + 1] = a.y;
                        z[4 * q + 2] = a.z; z[4 * q + 3] = a.w;
                    }
                } else {
#pragma unroll
                    for (int q = 0; q < 16; q++) z[q] = 0.0f;
                }
            }
#pragma unroll
            for (int half = 0; half < 2; half++) {   // two 16B chunks
                uint32_t hi[4], lo[4];
#pragma unroll
                for (int e = 0; e < 4; e++)
                    split2(z[8 * half + 2 * e], z[8 * half + 2 * e + 1], hi[e], lo[e]);
                int kb = tq * 2 + half;
                uint32_t off = (uint32_t)r * 128 + ((kb ^ (r & 7)) << 4);
                *(uint4*)(sAhi + off) = make_uint4(hi[0], hi[1], hi[2], hi[3]);
                *(uint4*)(sAlo + off) = make_uint4(lo[0], lo[1], lo[2], lo[3]);
            }
        }
        // ---- load B tile: coalesced, 8 threads per row ----
        {
            int j = tid & 7;                       // chunk id
#pragma unroll
            for (int pass = 0; pass < 8; pass++) {
                int n = pass * 32 + (tid >> 3);    // 0..255
                size_t goff = (size_t)(n0 + n) * Kfull + k0 + j * 8;
                uint4 hv = *(const uint4*)(g_Bhi + goff);
                uint4 lv = *(const uint4*)(g_Blo + goff);
                uint32_t off = (uint32_t)n * 128 + ((j ^ (n & 7)) << 4);
                *(uint4*)(sBhi + off) = hv;
                *(uint4*)(sBlo + off) = lv;
            }
        }
        __syncthreads();

        // ---- mma: 4 ksteps x (2 mfrag x 8 nfrag) x 3 passes ----
#pragma unroll
        for (int ks = 0; ks < 4; ks++) {
            uint32_t a_hi[2][4], a_lo[2][4];
#pragma unroll
            for (int mf = 0; mf < 2; mf++) {
                int row = wm * 32 + mf * 16 + (lsub & 1) * 8 + lrr;
                int kb  = ks * 2 + (lsub >> 1);
                uint32_t addr = (uint32_t)row * 128 + ((kb ^ (row & 7)) << 4);
                ldsm4(a_hi[mf], uAhi + addr);
                ldsm4(a_lo[mf], uAlo + addr);
            }
#pragma unroll
            for (int gi = 0; gi < 4; gi++) {       // nfrag pairs
                int n  = wn * 64 + (gi * 2 + (lsub & 1)) * 8 + lrr;
                int kb = ks * 2 + (lsub >> 1);
                uint32_t addr = (uint32_t)n * 128 + ((kb ^ (n & 7)) << 4);
                uint32_t bh[4], bl[4];
                ldsm4(bh, uBhi + addr);
                ldsm4(bl, uBlo + addr);
#pragma unroll
                for (int mf = 0; mf < 2; mf++) {
                    mma16816(c[mf][2 * gi],     a_hi[mf], bh[0], bh[2]);
                    mma16816(c[mf][2 * gi + 1], a_hi[mf], bh[1], bh[3]);
                    mma16816(c[mf][2 * gi],     a_hi[mf], bl[0], bl[2]);
                    mma16816(c[mf][2 * gi + 1], a_hi[mf], bl[1], bl[3]);
                    mma16816(c[mf][2 * gi],     a_lo[mf], bh[0], bh[2]);
                    mma16816(c[mf][2 * gi + 1], a_lo[mf], bh[1], bh[3]);
                }
            }
        }
    }

    // ---- epilogue ----
    const int qr = lane >> 2;          // 0..7
    const int qc = (lane & 3) * 2;     // 0,2,4,6
#pragma unroll
    for (int mf = 0; mf < 2; mf++) {
#pragma unroll
        for (int half = 0; half < 2; half++) {
            int rowLocal = wm * 32 + mf * 16 + half * 8 + qr;
            if (GATHER) {
                int d = sDst[rowLocal];
#pragma unroll
                for (int nf = 0; nf < 8; nf++) {
                    int col = wn * 64 + nf * 8 + qc;
                    float v0 = c[mf][nf][2 * half]     + sB2[col];
                    float v1 = c[mf][nf][2 * half + 1] + sB2[col + 1];
                    atomicMaxF(&g_seg[(size_t)d * FDIM + col],     v0);
                    atomicMaxF(&g_seg[(size_t)d * FDIM + col + 1], v1);
                }
            } else {
                int row = m0 + rowLocal;
                if (row < M) {
#pragma unroll
                    for (int nf = 0; nf < 8; nf++) {
                        int col = n0 + wn * 64 + nf * 8 + qc;
                        float2 v = make_float2(c[mf][nf][2 * half], c[mf][nf][2 * half + 1]);
                        *(float2*)(g_AB + (size_t)row * ABW + col) = v;
                    }
                }
            }
        }
    }
}

// ============================================================================
// layer-3 edge kernel (W2 is 256x3): one warp per edge
// ============================================================================
__global__ void edge3_kernel(const int* __restrict__ eidx, const float* __restrict__ b1,
                             const float* __restrict__ W3, const float* __restrict__ b2) {
    __shared__ float sW[768];
    __shared__ float sB1[256];
    int tid = threadIdx.x;
    for (int i = tid; i < 768; i += 256) sW[i] = W3[i];
    sB1[tid] = b1[tid];
    __syncthreads();
    int warp = tid >> 5, lane = tid & 31;
    int e = blockIdx.x * 8 + warp;
    int s = eidx[e], d = eidx[N_EDGES + e];
    const float* Ad = &g_AB[(size_t)d * ABW];
    const float* Bs = &g_AB[(size_t)s * ABW + 256];
    float s0 = 0.f, s1 = 0.f, s2 = 0.f;
#pragma unroll
    for (int k = lane; k < 256; k += 32) {
        float z = fmaxf(Ad[k] + Bs[k] + sB1[k], 0.0f);
        s0 = fmaf(z, sW[k * 3 + 0], s0);
        s1 = fmaf(z, sW[k * 3 + 1], s1);
        s2 = fmaf(z, sW[k * 3 + 2], s2);
    }
#pragma unroll
    for (int o = 16; o > 0; o >>= 1) {
        s0 += __shfl_down_sync(0xffffffff, s0, o);
        s1 += __shfl_down_sync(0xffffffff, s1, o);
        s2 += __shfl_down_sync(0xffffffff, s2, o);
    }
    if (lane == 0) {
        atomicMaxF(&g_seg[(size_t)d * 3 + 0], s0 + b2[0]);
        atomicMaxF(&g_seg[(size_t)d * 3 + 1], s1 + b2[1]);
        atomicMaxF(&g_seg[(size_t)d * 3 + 2], s2 + b2[2]);
    }
}

__global__ void fin12_kernel() {
    int i = blockIdx.x, j = threadIdx.x;
    float v = g_seg[(size_t)i * FDIM + j];
    g_hcat[(size_t)i * HCW + j] = (v > 0.0f) ? v : 0.0f;
}

__global__ void fin3_kernel(const float* __restrict__ t, float* __restrict__ out) {
    int idx = blockIdx.x * 256 + threadIdx.x;
    if (idx >= N_NODES * 3) return;
    int i = idx / 3;
    const float ln_sigma = 3.2188758248682006f;   // ln 25
    float tt = t[i];
    float sd = sqrtf((expf(2.0f * tt * ln_sigma) - 1.0f) / (2.0f * ln_sigma));
    float v = g_seg[idx];
    if (!isfinite(v)) v = 0.0f;
    out[idx] = v / (sd + 1e-7f);
}

// ============================================================================
extern "C" void kernel_launch(void* const* d_in, const int* in_sizes, int n_in,
                              void* d_out, int out_size) {
    const float* x    = (const float*)d_in[0];
    const int*   eidx = (const int*)d_in[1];    // int32 (JAX x64 disabled)
    const float* t    = (const float*)d_in[2];
    const float* emb  = (const float*)d_in[3];
    const float* encW = (const float*)d_in[4];
    const float* encb = (const float*)d_in[5];
    const float* fw   = (const float*)d_in[6];
    const float* teW  = (const float*)d_in[7];
    const float* teb  = (const float*)d_in[8];
    const float* W1[3] = {(const float*)d_in[9],  (const float*)d_in[13], (const float*)d_in[17]};
    const float* b1[3] = {(const float*)d_in[10], (const float*)d_in[14], (const float*)d_in[18]};
    const float* W2[3] = {(const float*)d_in[11], (const float*)d_in[15], (const float*)d_in[19]};
    const float* b2[3] = {(const float*)d_in[12], (const float*)d_in[16], (const float*)d_in[20]};
    float* out = (float*)d_out;
    (void)in_sizes; (void)n_in; (void)out_size;

    cudaFuncSetAttribute(mma_gemm<false>, cudaFuncAttributeMaxDynamicSharedMemorySize, DSMEM);
    cudaFuncSetAttribute(mma_gemm<true>,  cudaFuncAttributeMaxDynamicSharedMemorySize, DSMEM);

    temb_kernel<<<N_NODES / 8, 256>>>(t, fw, teW, teb);
    enc_kernel<<<N_NODES, 256>>>(x, encW, encb, emb);

    dim3 gNode((N_NODES + BM - 1) / BM, ABW / BN);   // 157 x 2
    dim3 gEdge(N_EDGES / BM, 1);                     // 2500 x 1

    for (int l = 0; l < 3; l++) {
        prepWc_kernel<<<(512 * 768) / 256, 256>>>(W1[l]);
        mma_gemm<false><<<gNode, 256, DSMEM>>>(N_NODES, HCW, nullptr, nullptr, nullptr);
        if (l < 2) {
            prepW2_kernel<<<(256 * 256) / 256, 256>>>(W2[l]);
            init_kernel<<<(N_NODES * FDIM) / 256, 256>>>(N_NODES * FDIM);
            mma_gemm<true><<<gEdge, 256, DSMEM>>>(N_EDGES, FDIM, eidx, b1[l], b2[l]);
            fin12_kernel<<<N_NODES, 256>>>();
        } else {
            init_kernel<<<(N_NODES * 3 + 255) / 256, 256>>>(N_NODES * 3);
            edge3_kernel<<<N_EDGES / 8, 256>>>(eidx, b1[l], W2[l], b2[l]);
            fin3_kernel<<<(N_NODES * 3 + 255) / 256, 256>>>(t, out);
        }
    }
}

// round 6
// speedup vs baseline: 1.9406x; 1.0027x over previous
#include <cuda_runtime.h>
#include <cuda_bf16.h>
#include <math.h>
#include <stdint.h>

#define N_NODES 10000
#define N_EDGES 160000
#define FDIM    256
#define HCW     768   // hcat: [h(256) | temb(256) | emb_pcs(256)]
#define ABW     512   // [A(256) | B(256)] per node

// tiling: block 64(M) x 256(N), K-chunk 64, 8 warps (2m x 4n), warp 32x64
#define BM   64
#define BN   256
#define KC   64
#define A_TILE (BM * KC * 2)                   // 8192 B per bf16 A tile
#define B_TILE (BN * KC * 2)                   // 32768 B per bf16 B tile
#define STAGE  (2 * A_TILE + 2 * B_TILE)       // 81920 B per pipeline stage
#define DSMEM  (2 * STAGE + 128)               // double-buffered

// -------- device scratch ----------------------------------------------------
__device__ __align__(16) float g_hcat[N_NODES * HCW];
__device__ __align__(16) float g_AB  [N_NODES * ABW];
__device__ __align__(16) float g_seg [N_NODES * FDIM];
__device__ __align__(16) __nv_bfloat16 g_Bhi[512 * 768];   // W^T hi  [n][k]
__device__ __align__(16) __nv_bfloat16 g_Blo[512 * 768];   // W^T lo  [n][k]

// -------- helpers -----------------------------------------------------------
__device__ __forceinline__ void atomicMaxF(float* addr, float v) {
    if (v >= 0.0f) atomicMax((int*)addr, __float_as_int(v));
    else           atomicMin((unsigned int*)addr, __float_as_uint(v));
}
__device__ __forceinline__ uint32_t smem_u32(const void* p) {
    uint32_t a;
    asm("{ .reg .u64 t; cvta.to.shared.u64 t, %1; cvt.u32.u64 %0, t; }" : "=r"(a) : "l"(p));
    return a;
}
__device__ __forceinline__ void ldsm4(uint32_t* r, uint32_t addr) {
    asm volatile("ldmatrix.sync.aligned.m8n8.x4.shared.b16 {%0,%1,%2,%3}, [%4];"
                 : "=r"(r[0]), "=r"(r[1]), "=r"(r[2]), "=r"(r[3]) : "r"(addr));
}
__device__ __forceinline__ void mma16816(float* c, const uint32_t* a,
                                         uint32_t b0, uint32_t b1) {
    asm volatile("mma.sync.aligned.m16n8k16.row.col.f32.bf16.bf16.f32 "
                 "{%0,%1,%2,%3}, {%4,%5,%6,%7}, {%8,%9}, {%0,%1,%2,%3};"
                 : "+f"(c[0]), "+f"(c[1]), "+f"(c[2]), "+f"(c[3])
                 : "r"(a[0]), "r"(a[1]), "r"(a[2]), "r"(a[3]), "r"(b0), "r"(b1));
}
__device__ __forceinline__ void cp16(uint32_t daddr, const void* gptr) {
    asm volatile("cp.async.cg.shared.global [%0], [%1], 16;"
                 :: "r"(daddr), "l"(gptr) : "memory");
}
#define CP_COMMIT() asm volatile("cp.async.commit_group;" ::: "memory")
#define CP_WAIT0()  asm volatile("cp.async.wait_group 0;" ::: "memory")

// bf16 hi/lo split of 2 floats -> packed uint32 hi, lo
__device__ __forceinline__ void split2(float z0, float z1, uint32_t& hi, uint32_t& lo) {
    __nv_bfloat16 h0 = __float2bfloat16(z0), h1 = __float2bfloat16(z1);
    __nv_bfloat16 l0 = __float2bfloat16(z0 - __bfloat162float(h0));
    __nv_bfloat16 l1 = __float2bfloat16(z1 - __bfloat162float(h1));
    hi = (uint32_t)__bfloat16_as_ushort(h0) | ((uint32_t)__bfloat16_as_ushort(h1) << 16);
    lo = (uint32_t)__bfloat16_as_ushort(l0) | ((uint32_t)__bfloat16_as_ushort(l1) << 16);
}

// ============================================================================
// small kernels
// ============================================================================
__global__ void temb_kernel(const float* __restrict__ t, const float* __restrict__ fw,
                            const float* __restrict__ teW, const float* __restrict__ teb) {
    __shared__ float v[8][256];
    int j = threadIdx.x, i0 = blockIdx.x * 8;
    if (j < 128) {
        float f = fw[j] * 6.283185307179586f;
#pragma unroll
        for (int r = 0; r < 8; r++) {
            float p = t[i0 + r] * f;
            v[r][j] = sinf(p); v[r][j + 128] = cosf(p);
        }
    }
    __syncthreads();
    float acc[8]; float bb = teb[j];
#pragma unroll
    for (int r = 0; r < 8; r++) acc[r] = bb;
    for (int k = 0; k < 256; k++) {
        float w = teW[k * 256 + j];
#pragma unroll
        for (int r = 0; r < 8; r++) acc[r] = fmaf(v[r][k], w, acc[r]);
    }
#pragma unroll
    for (int r = 0; r < 8; r++) {
        float a = acc[r];
        a = a / (1.0f + expf(-a));
        g_hcat[(size_t)(i0 + r) * HCW + 256 + j] = a;
    }
}

__global__ void enc_kernel(const float* __restrict__ x, const float* __restrict__ encW,
                           const float* __restrict__ encb, const float* __restrict__ emb) {
    int i = blockIdx.x, j = threadIdx.x;
    float h = encb[j];
    h = fmaf(x[i * 3 + 0], encW[0 * 256 + j], h);
    h = fmaf(x[i * 3 + 1], encW[1 * 256 + j], h);
    h = fmaf(x[i * 3 + 2], encW[2 * 256 + j], h);
    g_hcat[(size_t)i * HCW + j]       = h;
    g_hcat[(size_t)i * HCW + 512 + j] = emb[(size_t)i * 256 + j];
}

// Wc^T hi/lo [512 n][768 k]: n<256 -> W1top-W1bot col n ; else W1bot col n-256
__global__ void prepWc_kernel(const float* __restrict__ W1) {
    int idx = blockIdx.x * 256 + threadIdx.x;     // 512*768
    int n = idx / 768, k = idx % 768;
    float v = (n < 256) ? (W1[k * 256 + n] - W1[(768 + k) * 256 + n])
                        : W1[(768 + k) * 256 + (n - 256)];
    __nv_bfloat16 h = __float2bfloat16(v);
    g_Bhi[idx] = h;
    g_Blo[idx] = __float2bfloat16(v - __bfloat162float(h));
}

// W2^T hi/lo [256 n][256 k]
__global__ void prepW2_kernel(const float* __restrict__ W2) {
    int idx = blockIdx.x * 256 + threadIdx.x;     // 256*256
    int n = idx / 256, k = idx % 256;
    float v = W2[k * 256 + n];
    __nv_bfloat16 h = __float2bfloat16(v);
    g_Bhi[idx] = h;
    g_Blo[idx] = __float2bfloat16(v - __bfloat162float(h));
}

__global__ void init_kernel(int n) {
    int idx = blockIdx.x * 256 + threadIdx.x;
    if (idx < n) g_seg[idx] = __int_as_float(0xff800000);
}

// ============================================================================
// mma.sync bf16x3 GEMM — double-buffered software pipeline:
//   wait(B c) -> sync -> prefetch A(c+1) LDG + cp.async B(c+1) -> mma(c)
//   -> split/store A(c+1)
//   GATHER=false: g_AB[M,512] = hcat[M,768] @ Wc^T       (Kfull=768)
//   GATHER=true : Z = relu(A[dst]+B[src]+b1) [64,256];  seg max= Z @ W2^T
// smem swizzle: 16B chunk kb (0..7) stored at kb ^ (row & 7)
// ============================================================================
template <bool GATHER>
__global__ __launch_bounds__(256)
void mma_gemm(int M, int Kfull,
              const int* __restrict__ eidx,
              const float* __restrict__ b1,
              const float* __restrict__ b2) {
    extern __shared__ __align__(128) char dsm[];
    char* sbase = (char*)(((uintptr_t)dsm + 127) & ~(uintptr_t)127);
    const uint32_t usm = smem_u32(sbase);

    __shared__ int   sSrc[BM];
    __shared__ int   sDst[BM];
    __shared__ __align__(16) float sB1[256];
    __shared__ float sB2[256];

    const int tid  = threadIdx.x;
    const int wid  = tid >> 5, lane = tid & 31;
    const int wm   = wid & 1;            // m group of 32
    const int wn   = wid >> 1;           // n group of 64
    const int m0   = blockIdx.x * BM;
    const int n0   = blockIdx.y * BN;
    const int nChunks = Kfull / KC;

    if (GATHER) {
        if (tid < BM) {
            int e = m0 + tid;
            sSrc[tid] = eidx[e];
            sDst[tid] = eidx[N_EDGES + e];
        }
        sB1[tid] = b1[tid];
        sB2[tid] = b2[tid];
    }
    __syncthreads();                      // sSrc/sDst/sB1 visible before A(0)

    // ---- A build assignment: 4 threads per row, 16 k-values each ----
    const int ar = tid >> 2;              // 0..63 local row
    const int tq = tid & 3;               // k quarter
    const int adn = GATHER ? sDst[ar] : 0;
    const int asn = GATHER ? sSrc[ar] : 0;

    float zr0[16], zr1[16];               // prefetched raw A data

    // issue LDGs for chunk cix's A data into zr regs
    auto ldA = [&](int cix) {
        const int k0 = cix * KC;
        if (GATHER) {
            const float4* pA = (const float4*)(g_AB + (size_t)adn * ABW + k0 + tq * 16);
            const float4* pB = (const float4*)(g_AB + (size_t)asn * ABW + 256 + k0 + tq * 16);
#pragma unroll
            for (int q = 0; q < 4; q++) {
                float4 a = pA[q], b = pB[q];
                zr0[4*q+0] = a.x; zr0[4*q+1] = a.y; zr0[4*q+2] = a.z; zr0[4*q+3] = a.w;
                zr1[4*q+0] = b.x; zr1[4*q+1] = b.y; zr1[4*q+2] = b.z; zr1[4*q+3] = b.w;
            }
        } else {
            int row = m0 + ar;
            if (row < M) {
                const float4* p = (const float4*)(g_hcat + (size_t)row * HCW + k0 + tq * 16);
#pragma unroll
                for (int q = 0; q < 4; q++) {
                    float4 a = p[q];
                    zr0[4*q+0] = a.x; zr0[4*q+1] = a.y; zr0[4*q+2] = a.z; zr0[4*q+3] = a.w;
                }
            } else {
#pragma unroll
                for (int q = 0; q < 16; q++) zr0[q] = 0.0f;
            }
        }
    };
    // convert + store prefetched A data into stage s
    auto stA = [&](int cix, int s) {
        char* pAhi = sbase + s * STAGE;
        char* pAlo = pAhi + A_TILE;
        float z[16];
        if (GATHER) {
            const int k0 = cix * KC;
#pragma unroll
            for (int q = 0; q < 16; q++)
                z[q] = fmaxf(zr0[q] + zr1[q] + sB1[k0 + tq * 16 + q], 0.0f);
        } else {
#pragma unroll
            for (int q = 0; q < 16; q++) z[q] = zr0[q];
        }
#pragma unroll
        for (int half = 0; half < 2; half++) {
            uint32_t hi[4], lo[4];
#pragma unroll
            for (int e = 0; e < 4; e++)
                split2(z[8*half + 2*e], z[8*half + 2*e + 1], hi[e], lo[e]);
            int kb = tq * 2 + half;
            uint32_t off = (uint32_t)ar * 128 + ((kb ^ (ar & 7)) << 4);
            *(uint4*)(pAhi + off) = make_uint4(hi[0], hi[1], hi[2], hi[3]);
            *(uint4*)(pAlo + off) = make_uint4(lo[0], lo[1], lo[2], lo[3]);
        }
    };
    // cp.async B tile for chunk cix into stage s, then commit
    auto cpB = [&](int cix, int s) {
        const int k0 = cix * KC;
        const uint32_t uBh = usm + s * STAGE + 2 * A_TILE;
        const uint32_t uBl = uBh + B_TILE;
        int j = tid & 7;
#pragma unroll
        for (int pass = 0; pass < 8; pass++) {
            int n = pass * 32 + (tid >> 3);
            size_t goff = (size_t)(n0 + n) * Kfull + k0 + j * 8;
            uint32_t off = (uint32_t)n * 128 + ((j ^ (n & 7)) << 4);
            cp16(uBh + off, g_Bhi + goff);
            cp16(uBl + off, g_Blo + goff);
        }
        CP_COMMIT();
    };

    float c[2][8][4];
#pragma unroll
    for (int i = 0; i < 2; i++)
#pragma unroll
        for (int j = 0; j < 8; j++)
#pragma unroll
            for (int q = 0; q < 4; q++) c[i][j][q] = 0.0f;

    const int lsub = lane >> 3, lrr = lane & 7;

    // ---- prologue: stage 0 ----
    ldA(0);
    cpB(0, 0);
    stA(0, 0);

    for (int cix = 0; cix < nChunks; cix++) {
        const int cur = cix & 1, nxt = cur ^ 1;
        CP_WAIT0();            // B(cix) resident (nothing newer committed yet)
        __syncthreads();       // A(cix) stores visible; stage[nxt] free

        const bool more = (cix + 1 < nChunks);
        if (more) {
            ldA(cix + 1);      // LDGs in flight under the mma below
            cpB(cix + 1, nxt); // cp.async in flight under the mma below
        }

        const uint32_t uAh = usm + cur * STAGE;
        const uint32_t uAl = uAh + A_TILE;
        const uint32_t uBh = uAh + 2 * A_TILE;
        const uint32_t uBl = uBh + B_TILE;

#pragma unroll
        for (int ks = 0; ks < 4; ks++) {
            uint32_t a_hi[2][4], a_lo[2][4];
#pragma unroll
            for (int mf = 0; mf < 2; mf++) {
                int row = wm * 32 + mf * 16 + (lsub & 1) * 8 + lrr;
                int kb  = ks * 2 + (lsub >> 1);
                uint32_t addr = (uint32_t)row * 128 + ((kb ^ (row & 7)) << 4);
                ldsm4(a_hi[mf], uAh + addr);
                ldsm4(a_lo[mf], uAl + addr);
            }
#pragma unroll
            for (int gi = 0; gi < 4; gi++) {
                int n  = wn * 64 + (gi * 2 + (lsub & 1)) * 8 + lrr;
                int kb = ks * 2 + (lsub >> 1);
                uint32_t addr = (uint32_t)n * 128 + ((kb ^ (n & 7)) << 4);
                uint32_t bh[4], bl[4];
                ldsm4(bh, uBh + addr);
                ldsm4(bl, uBl + addr);
#pragma unroll
                for (int mf = 0; mf < 2; mf++) {
                    mma16816(c[mf][2*gi],     a_hi[mf], bh[0], bh[2]);
                    mma16816(c[mf][2*gi + 1], a_hi[mf], bh[1], bh[3]);
                    mma16816(c[mf][2*gi],     a_hi[mf], bl[0], bl[2]);
                    mma16816(c[mf][2*gi + 1], a_hi[mf], bl[1], bl[3]);
                    mma16816(c[mf][2*gi],     a_lo[mf], bh[0], bh[2]);
                    mma16816(c[mf][2*gi + 1], a_lo[mf], bh[1], bh[3]);
                }
            }
        }

        if (more) stA(cix + 1, nxt);
    }

    // ---- epilogue ----
    const int qr = lane >> 2;
    const int qc = (lane & 3) * 2;
#pragma unroll
    for (int mf = 0; mf < 2; mf++) {
#pragma unroll
        for (int half = 0; half < 2; half++) {
            int rowLocal = wm * 32 + mf * 16 + half * 8 + qr;
            if (GATHER) {
                int d = sDst[rowLocal];
#pragma unroll
                for (int nf = 0; nf < 8; nf++) {
                    int col = wn * 64 + nf * 8 + qc;
                    float v0 = c[mf][nf][2*half]     + sB2[col];
                    float v1 = c[mf][nf][2*half + 1] + sB2[col + 1];
                    atomicMaxF(&g_seg[(size_t)d * FDIM + col],     v0);
                    atomicMaxF(&g_seg[(size_t)d * FDIM + col + 1], v1);
                }
            } else {
                int row = m0 + rowLocal;
                if (row < M) {
#pragma unroll
                    for (int nf = 0; nf < 8; nf++) {
                        int col = n0 + wn * 64 + nf * 8 + qc;
                        float2 v = make_float2(c[mf][nf][2*half], c[mf][nf][2*half + 1]);
                        *(float2*)(g_AB + (size_t)row * ABW + col) = v;
                    }
                }
            }
        }
    }
}

// ============================================================================
// layer-3 edge kernel (W2 is 256x3): one warp per edge
// ============================================================================
__global__ void edge3_kernel(const int* __restrict__ eidx, const float* __restrict__ b1,
                             const float* __restrict__ W3, const float* __restrict__ b2) {
    __shared__ float sW[768];
    __shared__ float sB1[256];
    int tid = threadIdx.x;
    for (int i = tid; i < 768; i += 256) sW[i] = W3[i];
    sB1[tid] = b1[tid];
    __syncthreads();
    int warp = tid >> 5, lane = tid & 31;
    int e = blockIdx.x * 8 + warp;
    int s = eidx[e], d = eidx[N_EDGES + e];
    const float* Ad = &g_AB[(size_t)d * ABW];
    const float* Bs = &g_AB[(size_t)s * ABW + 256];
    float s0 = 0.f, s1 = 0.f, s2 = 0.f;
#pragma unroll
    for (int k = lane; k < 256; k += 32) {
        float z = fmaxf(Ad[k] + Bs[k] + sB1[k], 0.0f);
        s0 = fmaf(z, sW[k * 3 + 0], s0);
        s1 = fmaf(z, sW[k * 3 + 1], s1);
        s2 = fmaf(z, sW[k * 3 + 2], s2);
    }
#pragma unroll
    for (int o = 16; o > 0; o >>= 1) {
        s0 += __shfl_down_sync(0xffffffff, s0, o);
        s1 += __shfl_down_sync(0xffffffff, s1, o);
        s2 += __shfl_down_sync(0xffffffff, s2, o);
    }
    if (lane == 0) {
        atomicMaxF(&g_seg[(size_t)d * 3 + 0], s0 + b2[0]);
        atomicMaxF(&g_seg[(size_t)d * 3 + 1], s1 + b2[1]);
        atomicMaxF(&g_seg[(size_t)d * 3 + 2], s2 + b2[2]);
    }
}

__global__ void fin12_kernel() {
    int i = blockIdx.x, j = threadIdx.x;
    float v = g_seg[(size_t)i * FDIM + j];
    g_hcat[(size_t)i * HCW + j] = (v > 0.0f) ? v : 0.0f;
}

__global__ void fin3_kernel(const float* __restrict__ t, float* __restrict__ out) {
    int idx = blockIdx.x * 256 + threadIdx.x;
    if (idx >= N_NODES * 3) return;
    int i = idx / 3;
    const float ln_sigma = 3.2188758248682006f;   // ln 25
    float tt = t[i];
    float sd = sqrtf((expf(2.0f * tt * ln_sigma) - 1.0f) / (2.0f * ln_sigma));
    float v = g_seg[idx];
    if (!isfinite(v)) v = 0.0f;
    out[idx] = v / (sd + 1e-7f);
}

// ============================================================================
extern "C" void kernel_launch(void* const* d_in, const int* in_sizes, int n_in,
                              void* d_out, int out_size) {
    const float* x    = (const float*)d_in[0];
    const int*   eidx = (const int*)d_in[1];    // int32 (JAX x64 disabled)
    const float* t    = (const float*)d_in[2];
    const float* emb  = (const float*)d_in[3];
    const float* encW = (const float*)d_in[4];
    const float* encb = (const float*)d_in[5];
    const float* fw   = (const float*)d_in[6];
    const float* teW  = (const float*)d_in[7];
    const float* teb  = (const float*)d_in[8];
    const float* W1[3] = {(const float*)d_in[9],  (const float*)d_in[13], (const float*)d_in[17]};
    const float* b1[3] = {(const float*)d_in[10], (const float*)d_in[14], (const float*)d_in[18]};
    const float* W2[3] = {(const float*)d_in[11], (const float*)d_in[15], (const float*)d_in[19]};
    const float* b2[3] = {(const float*)d_in[12], (const float*)d_in[16], (const float*)d_in[20]};
    float* out = (float*)d_out;
    (void)in_sizes; (void)n_in; (void)out_size;

    cudaFuncSetAttribute(mma_gemm<false>, cudaFuncAttributeMaxDynamicSharedMemorySize, DSMEM);
    cudaFuncSetAttribute(mma_gemm<true>,  cudaFuncAttributeMaxDynamicSharedMemorySize, DSMEM);

    temb_kernel<<<N_NODES / 8, 256>>>(t, fw, teW, teb);
    enc_kernel<<<N_NODES, 256>>>(x, encW, encb, emb);

    dim3 gNode((N_NODES + BM - 1) / BM, ABW / BN);   // 157 x 2
    dim3 gEdge(N_EDGES / BM, 1);                     // 2500 x 1

    for (int l = 0; l < 3; l++) {
        prepWc_kernel<<<(512 * 768) / 256, 256>>>(W1[l]);
        mma_gemm<false><<<gNode, 256, DSMEM>>>(N_NODES, HCW, nullptr, nullptr, nullptr);
        if (l < 2) {
            prepW2_kernel<<<(256 * 256) / 256, 256>>>(W2[l]);
            init_kernel<<<(N_NODES * FDIM) / 256, 256>>>(N_NODES * FDIM);
            mma_gemm<true><<<gEdge, 256, DSMEM>>>(N_EDGES, FDIM, eidx, b1[l], b2[l]);
            fin12_kernel<<<N_NODES, 256>>>();
        } else {
            init_kernel<<<(N_NODES * 3 + 255) / 256, 256>>>(N_NODES * 3);
            edge3_kernel<<<N_EDGES / 8, 256>>>(eidx, b1[l], W2[l], b2[l]);
            fin3_kernel<<<(N_NODES * 3 + 255) / 256, 256>>>(t, out);
        }
    }
}

// round 7
// speedup vs baseline: 2.0408x; 1.0516x over previous
#include <cuda_runtime.h>
#include <cuda_bf16.h>
#include <math.h>
#include <stdint.h>

#define N_NODES 10000
#define N_EDGES 160000
#define FDIM    256
#define HCW     768   // hcat: [h(256) | temb(256) | emb_pcs(256)]
#define ABW     512   // [A(256) | B(256)] per node

// tiling: block 64(M) x 128(N), K-chunk 64, 8 warps (2m x 4n), warp 32x32
#define BM   64
#define BN   128
#define KC   64
#define A_TILE (BM * KC * 2)                   // 8192 B per bf16 A tile
#define B_TILE (BN * KC * 2)                   // 16384 B per bf16 B tile
#define STAGE  (2 * A_TILE + 2 * B_TILE)       // 49152 B per pipeline stage
#define DSMEM  (2 * STAGE + 128)               // double-buffered: ~96KB -> 2 CTA/SM

// -------- device scratch ----------------------------------------------------
__device__ __align__(16) float g_hcat[N_NODES * HCW];
__device__ __align__(16) float g_AB  [N_NODES * ABW];
__device__ __align__(16) float g_seg [N_NODES * FDIM];
__device__ __align__(16) __nv_bfloat16 g_Bhi[512 * 768];   // W^T hi  [n][k]
__device__ __align__(16) __nv_bfloat16 g_Blo[512 * 768];   // W^T lo  [n][k]

// -------- helpers -----------------------------------------------------------
__device__ __forceinline__ void atomicMaxF(float* addr, float v) {
    if (v >= 0.0f) atomicMax((int*)addr, __float_as_int(v));
    else           atomicMin((unsigned int*)addr, __float_as_uint(v));
}
__device__ __forceinline__ uint32_t smem_u32(const void* p) {
    uint32_t a;
    asm("{ .reg .u64 t; cvta.to.shared.u64 t, %1; cvt.u32.u64 %0, t; }" : "=r"(a) : "l"(p));
    return a;
}
__device__ __forceinline__ void ldsm4(uint32_t* r, uint32_t addr) {
    asm volatile("ldmatrix.sync.aligned.m8n8.x4.shared.b16 {%0,%1,%2,%3}, [%4];"
                 : "=r"(r[0]), "=r"(r[1]), "=r"(r[2]), "=r"(r[3]) : "r"(addr));
}
__device__ __forceinline__ void mma16816(float* c, const uint32_t* a,
                                         uint32_t b0, uint32_t b1) {
    asm volatile("mma.sync.aligned.m16n8k16.row.col.f32.bf16.bf16.f32 "
                 "{%0,%1,%2,%3}, {%4,%5,%6,%7}, {%8,%9}, {%0,%1,%2,%3};"
                 : "+f"(c[0]), "+f"(c[1]), "+f"(c[2]), "+f"(c[3])
                 : "r"(a[0]), "r"(a[1]), "r"(a[2]), "r"(a[3]), "r"(b0), "r"(b1));
}
__device__ __forceinline__ void cp16(uint32_t daddr, const void* gptr) {
    asm volatile("cp.async.cg.shared.global [%0], [%1], 16;"
                 :: "r"(daddr), "l"(gptr) : "memory");
}
#define CP_COMMIT() asm volatile("cp.async.commit_group;" ::: "memory")
#define CP_WAIT0()  asm volatile("cp.async.wait_group 0;" ::: "memory")

// bf16 hi/lo split of 2 floats -> packed uint32 hi, lo
__device__ __forceinline__ void split2(float z0, float z1, uint32_t& hi, uint32_t& lo) {
    __nv_bfloat16 h0 = __float2bfloat16(z0), h1 = __float2bfloat16(z1);
    __nv_bfloat16 l0 = __float2bfloat16(z0 - __bfloat162float(h0));
    __nv_bfloat16 l1 = __float2bfloat16(z1 - __bfloat162float(h1));
    hi = (uint32_t)__bfloat16_as_ushort(h0) | ((uint32_t)__bfloat16_as_ushort(h1) << 16);
    lo = (uint32_t)__bfloat16_as_ushort(l0) | ((uint32_t)__bfloat16_as_ushort(l1) << 16);
}

// ============================================================================
// small kernels
// ============================================================================
__global__ void temb_kernel(const float* __restrict__ t, const float* __restrict__ fw,
                            const float* __restrict__ teW, const float* __restrict__ teb) {
    __shared__ float v[8][256];
    int j = threadIdx.x, i0 = blockIdx.x * 8;
    if (j < 128) {
        float f = fw[j] * 6.283185307179586f;
#pragma unroll
        for (int r = 0; r < 8; r++) {
            float p = t[i0 + r] * f;
            v[r][j] = sinf(p); v[r][j + 128] = cosf(p);
        }
    }
    __syncthreads();
    float acc[8]; float bb = teb[j];
#pragma unroll
    for (int r = 0; r < 8; r++) acc[r] = bb;
    for (int k = 0; k < 256; k++) {
        float w = teW[k * 256 + j];
#pragma unroll
        for (int r = 0; r < 8; r++) acc[r] = fmaf(v[r][k], w, acc[r]);
    }
#pragma unroll
    for (int r = 0; r < 8; r++) {
        float a = acc[r];
        a = a / (1.0f + expf(-a));
        g_hcat[(size_t)(i0 + r) * HCW + 256 + j] = a;
    }
}

__global__ void enc_kernel(const float* __restrict__ x, const float* __restrict__ encW,
                           const float* __restrict__ encb, const float* __restrict__ emb) {
    int i = blockIdx.x, j = threadIdx.x;
    float h = encb[j];
    h = fmaf(x[i * 3 + 0], encW[0 * 256 + j], h);
    h = fmaf(x[i * 3 + 1], encW[1 * 256 + j], h);
    h = fmaf(x[i * 3 + 2], encW[2 * 256 + j], h);
    g_hcat[(size_t)i * HCW + j]       = h;
    g_hcat[(size_t)i * HCW + 512 + j] = emb[(size_t)i * 256 + j];
}

// Wc^T hi/lo [512 n][768 k]: n<256 -> W1top-W1bot col n ; else W1bot col n-256
__global__ void prepWc_kernel(const float* __restrict__ W1) {
    int idx = blockIdx.x * 256 + threadIdx.x;     // 512*768
    int n = idx / 768, k = idx % 768;
    float v = (n < 256) ? (W1[k * 256 + n] - W1[(768 + k) * 256 + n])
                        : W1[(768 + k) * 256 + (n - 256)];
    __nv_bfloat16 h = __float2bfloat16(v);
    g_Bhi[idx] = h;
    g_Blo[idx] = __float2bfloat16(v - __bfloat162float(h));
}

// W2^T hi/lo [256 n][256 k]
__global__ void prepW2_kernel(const float* __restrict__ W2) {
    int idx = blockIdx.x * 256 + threadIdx.x;     // 256*256
    int n = idx / 256, k = idx % 256;
    float v = W2[k * 256 + n];
    __nv_bfloat16 h = __float2bfloat16(v);
    g_Bhi[idx] = h;
    g_Blo[idx] = __float2bfloat16(v - __bfloat162float(h));
}

__global__ void init_kernel(int n) {
    int idx = blockIdx.x * 256 + threadIdx.x;
    if (idx < n) g_seg[idx] = __int_as_float(0xff800000);
}

// ============================================================================
// mma.sync bf16x3 GEMM — double-buffered pipeline, 2 CTAs/SM:
//   wait(B c) -> sync -> prefetch A(c+1) LDG + cp.async B(c+1) -> mma(c)
//   -> split/store A(c+1)
//   GATHER=false: g_AB[M,512] = hcat[M,768] @ Wc^T       (Kfull=768)
//   GATHER=true : Z = relu(A[dst]+B[src]+b1) [64,256];  seg max= Z @ W2^T
// smem swizzle: 16B chunk kb (0..7) stored at kb ^ (row & 7)
// ============================================================================
template <bool GATHER>
__global__ __launch_bounds__(256, 2)
void mma_gemm(int M, int Kfull,
              const int* __restrict__ eidx,
              const float* __restrict__ b1,
              const float* __restrict__ b2) {
    extern __shared__ __align__(128) char dsm[];
    char* sbase = (char*)(((uintptr_t)dsm + 127) & ~(uintptr_t)127);
    const uint32_t usm = smem_u32(sbase);

    __shared__ int   sSrc[BM];
    __shared__ int   sDst[BM];
    __shared__ __align__(16) float sB1[256];
    __shared__ float sB2[BN];

    const int tid  = threadIdx.x;
    const int wid  = tid >> 5, lane = tid & 31;
    const int wm   = wid & 1;            // m group of 32
    const int wn   = wid >> 1;           // n group of 32
    const int m0   = blockIdx.x * BM;
    const int n0   = blockIdx.y * BN;
    const int nChunks = Kfull / KC;

    if (GATHER) {
        if (tid < BM) {
            int e = m0 + tid;
            sSrc[tid] = eidx[e];
            sDst[tid] = eidx[N_EDGES + e];
        }
        sB1[tid] = b1[tid];
        if (tid < BN) sB2[tid] = b2[n0 + tid];
    }
    __syncthreads();                      // sSrc/sDst/sB1 visible before A(0)

    // ---- A build assignment: 4 threads per row, 16 k-values each ----
    const int ar = tid >> 2;              // 0..63 local row
    const int tq = tid & 3;               // k quarter
    const int adn = GATHER ? sDst[ar] : 0;
    const int asn = GATHER ? sSrc[ar] : 0;

    float zr0[16], zr1[16];               // prefetched raw A data

    auto ldA = [&](int cix) {
        const int k0 = cix * KC;
        if (GATHER) {
            const float4* pA = (const float4*)(g_AB + (size_t)adn * ABW + k0 + tq * 16);
            const float4* pB = (const float4*)(g_AB + (size_t)asn * ABW + 256 + k0 + tq * 16);
#pragma unroll
            for (int q = 0; q < 4; q++) {
                float4 a = pA[q], b = pB[q];
                zr0[4*q+0] = a.x; zr0[4*q+1] = a.y; zr0[4*q+2] = a.z; zr0[4*q+3] = a.w;
                zr1[4*q+0] = b.x; zr1[4*q+1] = b.y; zr1[4*q+2] = b.z; zr1[4*q+3] = b.w;
            }
        } else {
            int row = m0 + ar;
            if (row < M) {
                const float4* p = (const float4*)(g_hcat + (size_t)row * HCW + k0 + tq * 16);
#pragma unroll
                for (int q = 0; q < 4; q++) {
                    float4 a = p[q];
                    zr0[4*q+0] = a.x; zr0[4*q+1] = a.y; zr0[4*q+2] = a.z; zr0[4*q+3] = a.w;
                }
            } else {
#pragma unroll
                for (int q = 0; q < 16; q++) zr0[q] = 0.0f;
            }
        }
    };
    auto stA = [&](int cix, int s) {
        char* pAhi = sbase + s * STAGE;
        char* pAlo = pAhi + A_TILE;
        float z[16];
        if (GATHER) {
            const int k0 = cix * KC;
#pragma unroll
            for (int q = 0; q < 16; q++)
                z[q] = fmaxf(zr0[q] + zr1[q] + sB1[k0 + tq * 16 + q], 0.0f);
        } else {
#pragma unroll
            for (int q = 0; q < 16; q++) z[q] = zr0[q];
        }
#pragma unroll
        for (int half = 0; half < 2; half++) {
            uint32_t hi[4], lo[4];
#pragma unroll
            for (int e = 0; e < 4; e++)
                split2(z[8*half + 2*e], z[8*half + 2*e + 1], hi[e], lo[e]);
            int kb = tq * 2 + half;
            uint32_t off = (uint32_t)ar * 128 + ((kb ^ (ar & 7)) << 4);
            *(uint4*)(pAhi + off) = make_uint4(hi[0], hi[1], hi[2], hi[3]);
            *(uint4*)(pAlo + off) = make_uint4(lo[0], lo[1], lo[2], lo[3]);
        }
    };
    // cp.async B tile (BN=128 rows x 64 k) for chunk cix into stage s
    auto cpB = [&](int cix, int s) {
        const int k0 = cix * KC;
        const uint32_t uBh = usm + s * STAGE + 2 * A_TILE;
        const uint32_t uBl = uBh + B_TILE;
        int j = tid & 7;
#pragma unroll
        for (int pass = 0; pass < 4; pass++) {
            int n = pass * 32 + (tid >> 3);
            size_t goff = (size_t)(n0 + n) * Kfull + k0 + j * 8;
            uint32_t off = (uint32_t)n * 128 + ((j ^ (n & 7)) << 4);
            cp16(uBh + off, g_Bhi + goff);
            cp16(uBl + off, g_Blo + goff);
        }
        CP_COMMIT();
    };

    float c[2][4][4];
#pragma unroll
    for (int i = 0; i < 2; i++)
#pragma unroll
        for (int j = 0; j < 4; j++)
#pragma unroll
            for (int q = 0; q < 4; q++) c[i][j][q] = 0.0f;

    const int lsub = lane >> 3, lrr = lane & 7;

    // ---- prologue: stage 0 ----
    ldA(0);
    cpB(0, 0);
    stA(0, 0);

    for (int cix = 0; cix < nChunks; cix++) {
        const int cur = cix & 1, nxt = cur ^ 1;
        CP_WAIT0();            // B(cix) resident
        __syncthreads();       // A(cix) visible; stage[nxt] free

        const bool more = (cix + 1 < nChunks);
        if (more) {
            ldA(cix + 1);      // gather LDGs in flight under mma
            cpB(cix + 1, nxt); // cp.async in flight under mma
        }

        const uint32_t uAh = usm + cur * STAGE;
        const uint32_t uAl = uAh + A_TILE;
        const uint32_t uBh = uAh + 2 * A_TILE;
        const uint32_t uBl = uBh + B_TILE;

#pragma unroll
        for (int ks = 0; ks < 4; ks++) {
            uint32_t a_hi[2][4], a_lo[2][4];
            int kb = ks * 2 + (lsub >> 1);
#pragma unroll
            for (int mf = 0; mf < 2; mf++) {
                int row = wm * 32 + mf * 16 + (lsub & 1) * 8 + lrr;
                uint32_t addr = (uint32_t)row * 128 + ((kb ^ (row & 7)) << 4);
                ldsm4(a_hi[mf], uAh + addr);
                ldsm4(a_lo[mf], uAl + addr);
            }
#pragma unroll
            for (int gi = 0; gi < 2; gi++) {
                int n  = wn * 32 + (gi * 2 + (lsub & 1)) * 8 + lrr;
                uint32_t addr = (uint32_t)n * 128 + ((kb ^ (n & 7)) << 4);
                uint32_t bh[4], bl[4];
                ldsm4(bh, uBh + addr);
                ldsm4(bl, uBl + addr);
#pragma unroll
                for (int mf = 0; mf < 2; mf++) {
                    mma16816(c[mf][2*gi],     a_hi[mf], bh[0], bh[2]);
                    mma16816(c[mf][2*gi + 1], a_hi[mf], bh[1], bh[3]);
                    mma16816(c[mf][2*gi],     a_hi[mf], bl[0], bl[2]);
                    mma16816(c[mf][2*gi + 1], a_hi[mf], bl[1], bl[3]);
                    mma16816(c[mf][2*gi],     a_lo[mf], bh[0], bh[2]);
                    mma16816(c[mf][2*gi + 1], a_lo[mf], bh[1], bh[3]);
                }
            }
        }

        if (more) stA(cix + 1, nxt);
    }

    // ---- epilogue ----
    const int qr = lane >> 2;
    const int qc = (lane & 3) * 2;
#pragma unroll
    for (int mf = 0; mf < 2; mf++) {
#pragma unroll
        for (int half = 0; half < 2; half++) {
            int rowLocal = wm * 32 + mf * 16 + half * 8 + qr;
            if (GATHER) {
                int d = sDst[rowLocal];
#pragma unroll
                for (int nf = 0; nf < 4; nf++) {
                    int col = wn * 32 + nf * 8 + qc;
                    float v0 = c[mf][nf][2*half]     + sB2[col];
                    float v1 = c[mf][nf][2*half + 1] + sB2[col + 1];
                    atomicMaxF(&g_seg[(size_t)d * FDIM + n0 + col],     v0);
                    atomicMaxF(&g_seg[(size_t)d * FDIM + n0 + col + 1], v1);
                }
            } else {
                int row = m0 + rowLocal;
                if (row < M) {
#pragma unroll
                    for (int nf = 0; nf < 4; nf++) {
                        int col = n0 + wn * 32 + nf * 8 + qc;
                        float2 v = make_float2(c[mf][nf][2*half], c[mf][nf][2*half + 1]);
                        *(float2*)(g_AB + (size_t)row * ABW + col) = v;
                    }
                }
            }
        }
    }
}

// ============================================================================
// layer-3 edge kernel (W2 is 256x3): one warp per edge
// ============================================================================
__global__ void edge3_kernel(const int* __restrict__ eidx, const float* __restrict__ b1,
                             const float* __restrict__ W3, const float* __restrict__ b2) {
    __shared__ float sW[768];
    __shared__ float sB1[256];
    int tid = threadIdx.x;
    for (int i = tid; i < 768; i += 256) sW[i] = W3[i];
    sB1[tid] = b1[tid];
    __syncthreads();
    int warp = tid >> 5, lane = tid & 31;
    int e = blockIdx.x * 8 + warp;
    int s = eidx[e], d = eidx[N_EDGES + e];
    const float* Ad = &g_AB[(size_t)d * ABW];
    const float* Bs = &g_AB[(size_t)s * ABW + 256];
    float s0 = 0.f, s1 = 0.f, s2 = 0.f;
#pragma unroll
    for (int k = lane; k < 256; k += 32) {
        float z = fmaxf(Ad[k] + Bs[k] + sB1[k], 0.0f);
        s0 = fmaf(z, sW[k * 3 + 0], s0);
        s1 = fmaf(z, sW[k * 3 + 1], s1);
        s2 = fmaf(z, sW[k * 3 + 2], s2);
    }
#pragma unroll
    for (int o = 16; o > 0; o >>= 1) {
        s0 += __shfl_down_sync(0xffffffff, s0, o);
        s1 += __shfl_down_sync(0xffffffff, s1, o);
        s2 += __shfl_down_sync(0xffffffff, s2, o);
    }
    if (lane == 0) {
        atomicMaxF(&g_seg[(size_t)d * 3 + 0], s0 + b2[0]);
        atomicMaxF(&g_seg[(size_t)d * 3 + 1], s1 + b2[1]);
        atomicMaxF(&g_seg[(size_t)d * 3 + 2], s2 + b2[2]);
    }
}

__global__ void fin12_kernel() {
    int i = blockIdx.x, j = threadIdx.x;
    float v = g_seg[(size_t)i * FDIM + j];
    g_hcat[(size_t)i * HCW + j] = (v > 0.0f) ? v : 0.0f;
}

__global__ void fin3_kernel(const float* __restrict__ t, float* __restrict__ out) {
    int idx = blockIdx.x * 256 + threadIdx.x;
    if (idx >= N_NODES * 3) return;
    int i = idx / 3;
    const float ln_sigma = 3.2188758248682006f;   // ln 25
    float tt = t[i];
    float sd = sqrtf((expf(2.0f * tt * ln_sigma) - 1.0f) / (2.0f * ln_sigma));
    float v = g_seg[idx];
    if (!isfinite(v)) v = 0.0f;
    out[idx] = v / (sd + 1e-7f);
}

// ============================================================================
extern "C" void kernel_launch(void* const* d_in, const int* in_sizes, int n_in,
                              void* d_out, int out_size) {
    const float* x    = (const float*)d_in[0];
    const int*   eidx = (const int*)d_in[1];    // int32 (JAX x64 disabled)
    const float* t    = (const float*)d_in[2];
    const float* emb  = (const float*)d_in[3];
    const float* encW = (const float*)d_in[4];
    const float* encb = (const float*)d_in[5];
    const float* fw   = (const float*)d_in[6];
    const float* teW  = (const float*)d_in[7];
    const float* teb  = (const float*)d_in[8];
    const float* W1[3] = {(const float*)d_in[9],  (const float*)d_in[13], (const float*)d_in[17]};
    const float* b1[3] = {(const float*)d_in[10], (const float*)d_in[14], (const float*)d_in[18]};
    const float* W2[3] = {(const float*)d_in[11], (const float*)d_in[15], (const float*)d_in[19]};
    const float* b2[3] = {(const float*)d_in[12], (const float*)d_in[16], (const float*)d_in[20]};
    float* out = (float*)d_out;
    (void)in_sizes; (void)n_in; (void)out_size;

    cudaFuncSetAttribute(mma_gemm<false>, cudaFuncAttributeMaxDynamicSharedMemorySize, DSMEM);
    cudaFuncSetAttribute(mma_gemm<true>,  cudaFuncAttributeMaxDynamicSharedMemorySize, DSMEM);

    temb_kernel<<<N_NODES / 8, 256>>>(t, fw, teW, teb);
    enc_kernel<<<N_NODES, 256>>>(x, encW, encb, emb);

    dim3 gNode((N_NODES + BM - 1) / BM, ABW / BN);   // 157 x 4
    dim3 gEdge(N_EDGES / BM, FDIM / BN);             // 2500 x 2

    for (int l = 0; l < 3; l++) {
        prepWc_kernel<<<(512 * 768) / 256, 256>>>(W1[l]);
        mma_gemm<false><<<gNode, 256, DSMEM>>>(N_NODES, HCW, nullptr, nullptr, nullptr);
        if (l < 2) {
            prepW2_kernel<<<(256 * 256) / 256, 256>>>(W2[l]);
            init_kernel<<<(N_NODES * FDIM) / 256, 256>>>(N_NODES * FDIM);
            mma_gemm<true><<<gEdge, 256, DSMEM>>>(N_EDGES, FDIM, eidx, b1[l], b2[l]);
            fin12_kernel<<<N_NODES, 256>>>();
        } else {
            init_kernel<<<(N_NODES * 3 + 255) / 256, 256>>>(N_NODES * 3);
            edge3_kernel<<<N_EDGES / 8, 256>>>(eidx, b1[l], W2[l], b2[l]);
            fin3_kernel<<<(N_NODES * 3 + 255) / 256, 256>>>(t, out);
        }
    }
}

// round 8
// speedup vs baseline: 2.0452x; 1.0022x over previous
#include <cuda_runtime.h>
#include <cuda_bf16.h>
#include <math.h>
#include <stdint.h>

#define N_NODES 10000
#define N_EDGES 160000
#define FDIM    256
#define HCW     768   // hcat: [h(256) | temb(256) | emb_pcs(256)]
#define ABW     512   // [A(256) | B(256)] per node

// tiling: block 64(M) x 128(N), K-chunk 64, 8 warps (2m x 4n), warp 32x32
#define BM   64
#define BN   128
#define KC   64
#define A_TILE (BM * KC * 2)                   // 8192 B per bf16 A tile
#define B_TILE (BN * KC * 2)                   // 16384 B per bf16 B tile
#define STAGE  (2 * A_TILE + 2 * B_TILE)       // 49152 B per pipeline stage
#define DSMEM  (2 * STAGE + 128)               // double-buffered: ~96KB -> 2 CTA/SM

// -------- device scratch ----------------------------------------------------
__device__ __align__(16) float g_hcat[N_NODES * HCW];
__device__ __align__(16) float g_AB  [N_NODES * ABW];
__device__ __align__(16) float g_seg [N_NODES * FDIM];
__device__ __align__(16) __nv_bfloat16 g_Bhi[512 * 768];   // W^T hi  [n][k]
__device__ __align__(16) __nv_bfloat16 g_Blo[512 * 768];   // W^T lo  [n][k]

// -------- helpers -----------------------------------------------------------
__device__ __forceinline__ void atomicMaxF(float* addr, float v) {
    if (v >= 0.0f) atomicMax((int*)addr, __float_as_int(v));
    else           atomicMin((unsigned int*)addr, __float_as_uint(v));
}
__device__ __forceinline__ uint32_t smem_u32(const void* p) {
    uint32_t a;
    asm("{ .reg .u64 t; cvta.to.shared.u64 t, %1; cvt.u32.u64 %0, t; }" : "=r"(a) : "l"(p));
    return a;
}
__device__ __forceinline__ void ldsm4(uint32_t* r, uint32_t addr) {
    asm volatile("ldmatrix.sync.aligned.m8n8.x4.shared.b16 {%0,%1,%2,%3}, [%4];"
                 : "=r"(r[0]), "=r"(r[1]), "=r"(r[2]), "=r"(r[3]) : "r"(addr));
}
__device__ __forceinline__ void mma16816(float* c, const uint32_t* a,
                                         uint32_t b0, uint32_t b1) {
    asm volatile("mma.sync.aligned.m16n8k16.row.col.f32.bf16.bf16.f32 "
                 "{%0,%1,%2,%3}, {%4,%5,%6,%7}, {%8,%9}, {%0,%1,%2,%3};"
                 : "+f"(c[0]), "+f"(c[1]), "+f"(c[2]), "+f"(c[3])
                 : "r"(a[0]), "r"(a[1]), "r"(a[2]), "r"(a[3]), "r"(b0), "r"(b1));
}
__device__ __forceinline__ void cp16(uint32_t daddr, const void* gptr) {
    asm volatile("cp.async.cg.shared.global [%0], [%1], 16;"
                 :: "r"(daddr), "l"(gptr) : "memory");
}
#define CP_COMMIT() asm volatile("cp.async.commit_group;" ::: "memory")
#define CP_WAIT0()  asm volatile("cp.async.wait_group 0;" ::: "memory")

// bf16 hi/lo split of 2 floats -> packed uint32 hi, lo
__device__ __forceinline__ void split2(float z0, float z1, uint32_t& hi, uint32_t& lo) {
    __nv_bfloat16 h0 = __float2bfloat16(z0), h1 = __float2bfloat16(z1);
    __nv_bfloat16 l0 = __float2bfloat16(z0 - __bfloat162float(h0));
    __nv_bfloat16 l1 = __float2bfloat16(z1 - __bfloat162float(h1));
    hi = (uint32_t)__bfloat16_as_ushort(h0) | ((uint32_t)__bfloat16_as_ushort(h1) << 16);
    lo = (uint32_t)__bfloat16_as_ushort(l0) | ((uint32_t)__bfloat16_as_ushort(l1) << 16);
}

// ============================================================================
// small kernels
// ============================================================================
__global__ void temb_kernel(const float* __restrict__ t, const float* __restrict__ fw,
                            const float* __restrict__ teW, const float* __restrict__ teb) {
    __shared__ float v[8][256];
    int j = threadIdx.x, i0 = blockIdx.x * 8;
    if (j < 128) {
        float f = fw[j] * 6.283185307179586f;
#pragma unroll
        for (int r = 0; r < 8; r++) {
            float p = t[i0 + r] * f;
            v[r][j] = sinf(p); v[r][j + 128] = cosf(p);
        }
    }
    __syncthreads();
    float acc[8]; float bb = teb[j];
#pragma unroll
    for (int r = 0; r < 8; r++) acc[r] = bb;
    for (int k = 0; k < 256; k++) {
        float w = teW[k * 256 + j];
#pragma unroll
        for (int r = 0; r < 8; r++) acc[r] = fmaf(v[r][k], w, acc[r]);
    }
#pragma unroll
    for (int r = 0; r < 8; r++) {
        float a = acc[r];
        a = a / (1.0f + expf(-a));
        g_hcat[(size_t)(i0 + r) * HCW + 256 + j] = a;
    }
}

__global__ void enc_kernel(const float* __restrict__ x, const float* __restrict__ encW,
                           const float* __restrict__ encb, const float* __restrict__ emb) {
    int i = blockIdx.x, j = threadIdx.x;
    float h = encb[j];
    h = fmaf(x[i * 3 + 0], encW[0 * 256 + j], h);
    h = fmaf(x[i * 3 + 1], encW[1 * 256 + j], h);
    h = fmaf(x[i * 3 + 2], encW[2 * 256 + j], h);
    g_hcat[(size_t)i * HCW + j]       = h;
    g_hcat[(size_t)i * HCW + 512 + j] = emb[(size_t)i * 256 + j];
}

// Wc^T hi/lo [512 n][768 k]: n<256 -> W1top-W1bot col n ; else W1bot col n-256
__global__ void prepWc_kernel(const float* __restrict__ W1) {
    int idx = blockIdx.x * 256 + threadIdx.x;     // 512*768
    int n = idx / 768, k = idx % 768;
    float v = (n < 256) ? (W1[k * 256 + n] - W1[(768 + k) * 256 + n])
                        : W1[(768 + k) * 256 + (n - 256)];
    __nv_bfloat16 h = __float2bfloat16(v);
    g_Bhi[idx] = h;
    g_Blo[idx] = __float2bfloat16(v - __bfloat162float(h));
}

// W2^T hi/lo [256 n][256 k]
__global__ void prepW2_kernel(const float* __restrict__ W2) {
    int idx = blockIdx.x * 256 + threadIdx.x;     // 256*256
    int n = idx / 256, k = idx % 256;
    float v = W2[k * 256 + n];
    __nv_bfloat16 h = __float2bfloat16(v);
    g_Bhi[idx] = h;
    g_Blo[idx] = __float2bfloat16(v - __bfloat162float(h));
}

__global__ void init_kernel(int n) {
    int idx = blockIdx.x * 256 + threadIdx.x;
    if (idx < n) g_seg[idx] = __int_as_float(0xff800000);
}

// ============================================================================
// mma.sync bf16x3 GEMM — double-buffered pipeline, 2 CTAs/SM:
//   wait(B c) -> sync -> prefetch A(c+1) LDG + cp.async B(c+1) -> mma(c)
//   -> split/store A(c+1)
//   GATHER=false: g_AB[M,512] = hcat[M,768] @ Wc^T       (Kfull=768)
//   GATHER=true : Z = relu(A[dst]+B[src]+b1) [64,256];  seg max= Z @ W2^T
// smem swizzle: 16B chunk kb (0..7) stored at kb ^ (row & 7)
// ============================================================================
template <bool GATHER>
__global__ __launch_bounds__(256, 2)
void mma_gemm(int M, int Kfull,
              const int* __restrict__ eidx,
              const float* __restrict__ b1,
              const float* __restrict__ b2) {
    extern __shared__ __align__(128) char dsm[];
    char* sbase = (char*)(((uintptr_t)dsm + 127) & ~(uintptr_t)127);
    const uint32_t usm = smem_u32(sbase);

    __shared__ int   sSrc[BM];
    __shared__ int   sDst[BM];
    __shared__ __align__(16) float sB1[256];
    __shared__ float sB2[BN];

    const int tid  = threadIdx.x;
    const int wid  = tid >> 5, lane = tid & 31;
    const int wm   = wid & 1;            // m group of 32
    const int wn   = wid >> 1;           // n group of 32
    const int m0   = blockIdx.x * BM;
    const int n0   = blockIdx.y * BN;
    const int nChunks = Kfull / KC;

    if (GATHER) {
        if (tid < BM) {
            int e = m0 + tid;
            sSrc[tid] = eidx[e];
            sDst[tid] = eidx[N_EDGES + e];
        }
        sB1[tid] = b1[tid];
        if (tid < BN) sB2[tid] = b2[n0 + tid];
    }
    __syncthreads();                      // sSrc/sDst/sB1 visible before A(0)

    // ---- A build assignment: 4 threads per row, 16 k-values each ----
    const int ar = tid >> 2;              // 0..63 local row
    const int tq = tid & 3;               // k quarter
    const int adn = GATHER ? sDst[ar] : 0;
    const int asn = GATHER ? sSrc[ar] : 0;

    float zr0[16], zr1[16];               // prefetched raw A data

    auto ldA = [&](int cix) {
        const int k0 = cix * KC;
        if (GATHER) {
            const float4* pA = (const float4*)(g_AB + (size_t)adn * ABW + k0 + tq * 16);
            const float4* pB = (const float4*)(g_AB + (size_t)asn * ABW + 256 + k0 + tq * 16);
#pragma unroll
            for (int q = 0; q < 4; q++) {
                float4 a = pA[q], b = pB[q];
                zr0[4*q+0] = a.x; zr0[4*q+1] = a.y; zr0[4*q+2] = a.z; zr0[4*q+3] = a.w;
                zr1[4*q+0] = b.x; zr1[4*q+1] = b.y; zr1[4*q+2] = b.z; zr1[4*q+3] = b.w;
            }
        } else {
            int row = m0 + ar;
            if (row < M) {
                const float4* p = (const float4*)(g_hcat + (size_t)row * HCW + k0 + tq * 16);
#pragma unroll
                for (int q = 0; q < 4; q++) {
                    float4 a = p[q];
                    zr0[4*q+0] = a.x; zr0[4*q+1] = a.y; zr0[4*q+2] = a.z; zr0[4*q+3] = a.w;
                }
            } else {
#pragma unroll
                for (int q = 0; q < 16; q++) zr0[q] = 0.0f;
            }
        }
    };
    auto stA = [&](int cix, int s) {
        char* pAhi = sbase + s * STAGE;
        char* pAlo = pAhi + A_TILE;
        float z[16];
        if (GATHER) {
            const int k0 = cix * KC;
#pragma unroll
            for (int q = 0; q < 16; q++)
                z[q] = fmaxf(zr0[q] + zr1[q] + sB1[k0 + tq * 16 + q], 0.0f);
        } else {
#pragma unroll
            for (int q = 0; q < 16; q++) z[q] = zr0[q];
        }
#pragma unroll
        for (int half = 0; half < 2; half++) {
            uint32_t hi[4], lo[4];
#pragma unroll
            for (int e = 0; e < 4; e++)
                split2(z[8*half + 2*e], z[8*half + 2*e + 1], hi[e], lo[e]);
            int kb = tq * 2 + half;
            uint32_t off = (uint32_t)ar * 128 + ((kb ^ (ar & 7)) << 4);
            *(uint4*)(pAhi + off) = make_uint4(hi[0], hi[1], hi[2], hi[3]);
            *(uint4*)(pAlo + off) = make_uint4(lo[0], lo[1], lo[2], lo[3]);
        }
    };
    // cp.async B tile (BN=128 rows x 64 k) for chunk cix into stage s
    auto cpB = [&](int cix, int s) {
        const int k0 = cix * KC;
        const uint32_t uBh = usm + s * STAGE + 2 * A_TILE;
        const uint32_t uBl = uBh + B_TILE;
        int j = tid & 7;
#pragma unroll
        for (int pass = 0; pass < 4; pass++) {
            int n = pass * 32 + (tid >> 3);
            size_t goff = (size_t)(n0 + n) * Kfull + k0 + j * 8;
            uint32_t off = (uint32_t)n * 128 + ((j ^ (n & 7)) << 4);
            cp16(uBh + off, g_Bhi + goff);
            cp16(uBl + off, g_Blo + goff);
        }
        CP_COMMIT();
    };

    float c[2][4][4];
#pragma unroll
    for (int i = 0; i < 2; i++)
#pragma unroll
        for (int j = 0; j < 4; j++)
#pragma unroll
            for (int q = 0; q < 4; q++) c[i][j][q] = 0.0f;

    const int lsub = lane >> 3, lrr = lane & 7;

    // ---- prologue: stage 0 ----
    ldA(0);
    cpB(0, 0);
    stA(0, 0);

    for (int cix = 0; cix < nChunks; cix++) {
        const int cur = cix & 1, nxt = cur ^ 1;
        CP_WAIT0();            // B(cix) resident
        __syncthreads();       // A(cix) visible; stage[nxt] free

        const bool more = (cix + 1 < nChunks);
        if (more) {
            ldA(cix + 1);      // gather LDGs in flight under mma
            cpB(cix + 1, nxt); // cp.async in flight under mma
        }

        const uint32_t uAh = usm + cur * STAGE;
        const uint32_t uAl = uAh + A_TILE;
        const uint32_t uBh = uAh + 2 * A_TILE;
        const uint32_t uBl = uBh + B_TILE;

#pragma unroll
        for (int ks = 0; ks < 4; ks++) {
            uint32_t a_hi[2][4], a_lo[2][4];
            int kb = ks * 2 + (lsub >> 1);
#pragma unroll
            for (int mf = 0; mf < 2; mf++) {
                int row = wm * 32 + mf * 16 + (lsub & 1) * 8 + lrr;
                uint32_t addr = (uint32_t)row * 128 + ((kb ^ (row & 7)) << 4);
                ldsm4(a_hi[mf], uAh + addr);
                ldsm4(a_lo[mf], uAl + addr);
            }
#pragma unroll
            for (int gi = 0; gi < 2; gi++) {
                int n  = wn * 32 + (gi * 2 + (lsub & 1)) * 8 + lrr;
                uint32_t addr = (uint32_t)n * 128 + ((kb ^ (n & 7)) << 4);
                uint32_t bh[4], bl[4];
                ldsm4(bh, uBh + addr);
                ldsm4(bl, uBl + addr);
#pragma unroll
                for (int mf = 0; mf < 2; mf++) {
                    mma16816(c[mf][2*gi],     a_hi[mf], bh[0], bh[2]);
                    mma16816(c[mf][2*gi + 1], a_hi[mf], bh[1], bh[3]);
                    mma16816(c[mf][2*gi],     a_hi[mf], bl[0], bl[2]);
                    mma16816(c[mf][2*gi + 1], a_hi[mf], bl[1], bl[3]);
                    mma16816(c[mf][2*gi],     a_lo[mf], bh[0], bh[2]);
                    mma16816(c[mf][2*gi + 1], a_lo[mf], bh[1], bh[3]);
                }
            }
        }

        if (more) stA(cix + 1, nxt);
    }

    // ---- epilogue ----
    const int qr = lane >> 2;
    const int qc = (lane & 3) * 2;
#pragma unroll
    for (int mf = 0; mf < 2; mf++) {
#pragma unroll
        for (int half = 0; half < 2; half++) {
            int rowLocal = wm * 32 + mf * 16 + half * 8 + qr;
            if (GATHER) {
                int d = sDst[rowLocal];
#pragma unroll
                for (int nf = 0; nf < 4; nf++) {
                    int col = wn * 32 + nf * 8 + qc;
                    float v0 = c[mf][nf][2*half]     + sB2[col];
                    float v1 = c[mf][nf][2*half + 1] + sB2[col + 1];
                    atomicMaxF(&g_seg[(size_t)d * FDIM + n0 + col],     v0);
                    atomicMaxF(&g_seg[(size_t)d * FDIM + n0 + col + 1], v1);
                }
            } else {
                int row = m0 + rowLocal;
                if (row < M) {
#pragma unroll
                    for (int nf = 0; nf < 4; nf++) {
                        int col = n0 + wn * 32 + nf * 8 + qc;
                        float2 v = make_float2(c[mf][nf][2*half], c[mf][nf][2*half + 1]);
                        *(float2*)(g_AB + (size_t)row * ABW + col) = v;
                    }
                }
            }
        }
    }
}

// ============================================================================
// layer-3 edge kernel (W2 is 256x3): one warp per edge
// ============================================================================
__global__ void edge3_kernel(const int* __restrict__ eidx, const float* __restrict__ b1,
                             const float* __restrict__ W3, const float* __restrict__ b2) {
    __shared__ float sW[768];
    __shared__ float sB1[256];
    int tid = threadIdx.x;
    for (int i = tid; i < 768; i += 256) sW[i] = W3[i];
    sB1[tid] = b1[tid];
    __syncthreads();
    int warp = tid >> 5, lane = tid & 31;
    int e = blockIdx.x * 8 + warp;
    int s = eidx[e], d = eidx[N_EDGES + e];
    const float* Ad = &g_AB[(size_t)d * ABW];
    const float* Bs = &g_AB[(size_t)s * ABW + 256];
    float s0 = 0.f, s1 = 0.f, s2 = 0.f;
#pragma unroll
    for (int k = lane; k < 256; k += 32) {
        float z = fmaxf(Ad[k] + Bs[k] + sB1[k], 0.0f);
        s0 = fmaf(z, sW[k * 3 + 0], s0);
        s1 = fmaf(z, sW[k * 3 + 1], s1);
        s2 = fmaf(z, sW[k * 3 + 2], s2);
    }
#pragma unroll
    for (int o = 16; o > 0; o >>= 1) {
        s0 += __shfl_down_sync(0xffffffff, s0, o);
        s1 += __shfl_down_sync(0xffffffff, s1, o);
        s2 += __shfl_down_sync(0xffffffff, s2, o);
    }
    if (lane == 0) {
        atomicMaxF(&g_seg[(size_t)d * 3 + 0], s0 + b2[0]);
        atomicMaxF(&g_seg[(size_t)d * 3 + 1], s1 + b2[1]);
        atomicMaxF(&g_seg[(size_t)d * 3 + 2], s2 + b2[2]);
    }
}

__global__ void fin12_kernel() {
    int i = blockIdx.x, j = threadIdx.x;
    float v = g_seg[(size_t)i * FDIM + j];
    g_hcat[(size_t)i * HCW + j] = (v > 0.0f) ? v : 0.0f;
}

__global__ void fin3_kernel(const float* __restrict__ t, float* __restrict__ out) {
    int idx = blockIdx.x * 256 + threadIdx.x;
    if (idx >= N_NODES * 3) return;
    int i = idx / 3;
    const float ln_sigma = 3.2188758248682006f;   // ln 25
    float tt = t[i];
    float sd = sqrtf((expf(2.0f * tt * ln_sigma) - 1.0f) / (2.0f * ln_sigma));
    float v = g_seg[idx];
    if (!isfinite(v)) v = 0.0f;
    out[idx] = v / (sd + 1e-7f);
}

// ============================================================================
extern "C" void kernel_launch(void* const* d_in, const int* in_sizes, int n_in,
                              void* d_out, int out_size) {
    const float* x    = (const float*)d_in[0];
    const int*   eidx = (const int*)d_in[1];    // int32 (JAX x64 disabled)
    const float* t    = (const float*)d_in[2];
    const float* emb  = (const float*)d_in[3];
    const float* encW = (const float*)d_in[4];
    const float* encb = (const float*)d_in[5];
    const float* fw   = (const float*)d_in[6];
    const float* teW  = (const float*)d_in[7];
    const float* teb  = (const float*)d_in[8];
    const float* W1[3] = {(const float*)d_in[9],  (const float*)d_in[13], (const float*)d_in[17]};
    const float* b1[3] = {(const float*)d_in[10], (const float*)d_in[14], (const float*)d_in[18]};
    const float* W2[3] = {(const float*)d_in[11], (const float*)d_in[15], (const float*)d_in[19]};
    const float* b2[3] = {(const float*)d_in[12], (const float*)d_in[16], (const float*)d_in[20]};
    float* out = (float*)d_out;
    (void)in_sizes; (void)n_in; (void)out_size;

    cudaFuncSetAttribute(mma_gemm<false>, cudaFuncAttributeMaxDynamicSharedMemorySize, DSMEM);
    cudaFuncSetAttribute(mma_gemm<true>,  cudaFuncAttributeMaxDynamicSharedMemorySize, DSMEM);

    temb_kernel<<<N_NODES / 8, 256>>>(t, fw, teW, teb);
    enc_kernel<<<N_NODES, 256>>>(x, encW, encb, emb);

    dim3 gNode((N_NODES + BM - 1) / BM, ABW / BN);   // 157 x 4
    dim3 gEdge(N_EDGES / BM, FDIM / BN);             // 2500 x 2

    for (int l = 0; l < 3; l++) {
        prepWc_kernel<<<(512 * 768) / 256, 256>>>(W1[l]);
        mma_gemm<false><<<gNode, 256, DSMEM>>>(N_NODES, HCW, nullptr, nullptr, nullptr);
        if (l < 2) {
            prepW2_kernel<<<(256 * 256) / 256, 256>>>(W2[l]);
            init_kernel<<<(N_NODES * FDIM) / 256, 256>>>(N_NODES * FDIM);
            mma_gemm<true><<<gEdge, 256, DSMEM>>>(N_EDGES, FDIM, eidx, b1[l], b2[l]);
            fin12_kernel<<<N_NODES, 256>>>();
        } else {
            init_kernel<<<(N_NODES * 3 + 255) / 256, 256>>>(N_NODES * 3);
            edge3_kernel<<<N_EDGES / 8, 256>>>(eidx, b1[l], W2[l], b2[l]);
            fin3_kernel<<<(N_NODES * 3 + 255) / 256, 256>>>(t, out);
        }
    }
}